// round 1
// baseline (speedup 1.0000x reference)
#include <cuda_runtime.h>
#include <math.h>

// ---------------- problem constants ----------------
#define NB   128      // batch N
#define LT   256      // sequence length L
#define NJ   24       // joints
#define HD   32       // GAT hidden
#define FH   768      // LSTM hidden (24*32)
#define GG   3072     // 4*768 gates
#define BG   (NB*LT)  // 32768 graphs

// ---------------- scratch (device globals: allocation-free) ----------------
__device__ float g_X [(size_t)BG * FH];   // GAT output, row r = t*128 + n
__device__ float g_XW[(size_t)BG * GG];   // X @ W_ih^T, row r = t*128 + n
__device__ float g_gates[NB * GG];        // per-step recurrent partial h @ W_hh^T
__device__ float g_c[NB * FH];            // cell state

__constant__ int c_par[24] = {-1,0,0,0,1,2,3,4,5,6,7,8,9,9,9,12,13,14,16,17,18,19,20,21};

__device__ __forceinline__ float sigm(float x) { return 1.f / (1.f + expf(-x)); }

// ---------------- GAT: one warp per graph ----------------
// lane = hidden index h. xbuf holds x (tanh(pre)) then is overwritten row-by-row with xp.
__global__ __launch_bounds__(256) void gat_kernel(
    const float* __restrict__ src,
    const float* __restrict__ W_pre, const float* __restrict__ b_pre,
    const float* __restrict__ W_gat,
    const float* __restrict__ att_src, const float* __restrict__ att_dst,
    const float* __restrict__ b_gat,
    float* __restrict__ X)
{
    __shared__ float Wg[32 * 32];
    __shared__ float xbuf[8][24][32];   // x, then xp
    __shared__ float asd[8][24][2];     // a_src, a_dst per joint

    int tid = threadIdx.x;
    for (int i = tid; i < 1024; i += 256) Wg[i] = W_gat[i];
    __syncthreads();

    int w = tid >> 5, h = tid & 31;
    int b = blockIdx.x * 8 + w;          // graph id, b = n*256 + l
    int n = b >> 8, l = b & 255;

    const float* s = src + (size_t)b * 72;
    float w0 = W_pre[h], w1 = W_pre[32 + h], w2 = W_pre[64 + h], bp = b_pre[h];

    #pragma unroll
    for (int j = 0; j < 24; j++) {
        float v = fmaf(s[j*3+2], w2, fmaf(s[j*3+1], w1, fmaf(s[j*3+0], w0, bp)));
        xbuf[w][j][h] = tanhf(v);
    }
    __syncwarp();

    float asrc = att_src[h], adst = att_dst[h];
    #pragma unroll
    for (int j = 0; j < 24; j++) {
        float acc = 0.f;
        #pragma unroll
        for (int k = 0; k < 32; k++) acc = fmaf(xbuf[w][j][k], Wg[k*32 + h], acc);
        // reductions for attention coefficients
        float ps = acc * asrc, pd = acc * adst;
        #pragma unroll
        for (int o = 16; o > 0; o >>= 1) {
            ps += __shfl_xor_sync(0xffffffffu, ps, o);
            pd += __shfl_xor_sync(0xffffffffu, pd, o);
        }
        __syncwarp();                 // everyone done reading xbuf[w][j][*]
        xbuf[w][j][h] = acc;          // store xp in place
        if (h == 0) { asd[w][j][0] = ps; asd[w][j][1] = pd; }
    }
    __syncwarp();

    float bg = b_gat[h];
    float* xrow = X + (size_t)(l * 128 + n) * FH;   // row r = t*128 + n
    #pragma unroll
    for (int j = 0; j < 24; j++) {
        int p = c_par[j];
        float g;
        if (p < 0) {
            g = xbuf[w][j][h];   // softmax over single self edge = 1
        } else {
            float ad = asd[w][j][1];
            float es = ad + asd[w][j][0];
            float ep = ad + asd[w][p][0];
            es = es > 0.f ? es : 0.2f * es;   // leaky relu 0.2
            ep = ep > 0.f ? ep : 0.2f * ep;
            float m  = fmaxf(es, ep);
            float ws = expf(es - m), wp = expf(ep - m);
            float inv = 1.f / (ws + wp);
            g = (ws * xbuf[w][j][h] + wp * xbuf[w][p][h]) * inv;
        }
        xrow[j * 32 + h] = g + bg;
    }
}

// ---------------- generic SGEMM: C[m][n] = sum_k A[m*lda+k] * B[n*ldb+k] ----------------
template<int BM, int BN, int BK, int TM, int TN, int THREADS>
__global__ __launch_bounds__(THREADS) void sgemm_nt(
    const float* __restrict__ A, size_t lda,
    const float* __restrict__ B, size_t ldb,
    float* __restrict__ C, size_t ldc, int K)
{
    __shared__ float As[BK][BM + 1];
    __shared__ float Bs[BK][BN + 1];

    const int tid = threadIdx.x;
    const int m0 = blockIdx.y * BM;
    const int n0 = blockIdx.x * BN;
    const int CT = BN / TN;
    const int ty = tid / CT, tx = tid % CT;

    float acc[TM][TN];
    #pragma unroll
    for (int i = 0; i < TM; i++)
        #pragma unroll
        for (int j = 0; j < TN; j++) acc[i][j] = 0.f;

    for (int k0 = 0; k0 < K; k0 += BK) {
        #pragma unroll
        for (int i = tid; i < BM * BK; i += THREADS) {
            int r = i / BK, c = i % BK;
            As[c][r] = A[(size_t)(m0 + r) * lda + k0 + c];
        }
        #pragma unroll
        for (int i = tid; i < BN * BK; i += THREADS) {
            int r = i / BK, c = i % BK;
            Bs[c][r] = B[(size_t)(n0 + r) * ldb + k0 + c];
        }
        __syncthreads();

        #pragma unroll
        for (int kk = 0; kk < BK; kk++) {
            float af[TM], bf[TN];
            #pragma unroll
            for (int i = 0; i < TM; i++) af[i] = As[kk][ty * TM + i];
            #pragma unroll
            for (int j = 0; j < TN; j++) bf[j] = Bs[kk][tx * TN + j];
            #pragma unroll
            for (int i = 0; i < TM; i++)
                #pragma unroll
                for (int j = 0; j < TN; j++)
                    acc[i][j] = fmaf(af[i], bf[j], acc[i][j]);
        }
        __syncthreads();
    }

    #pragma unroll
    for (int i = 0; i < TM; i++) {
        float* crow = C + (size_t)(m0 + ty * TM + i) * ldc + n0 + tx * TN;
        #pragma unroll
        for (int j = 0; j < TN; j++) crow[j] = acc[i][j];
    }
}

// ---------------- fused LSTM pointwise ----------------
// gates = XW_t (+ rec if t>0) + b_ih + b_hh; update c; h -> out (time slice t).
__global__ __launch_bounds__(256) void lstm_point(
    const float* __restrict__ xw,    // g_XW + t*128*3072
    const float* __restrict__ rec,   // g_gates (valid iff t>0)
    const float* __restrict__ b_ih, const float* __restrict__ b_hh,
    float* __restrict__ out, float* __restrict__ c_state, int t)
{
    int idx = blockIdx.x * blockDim.x + threadIdx.x;   // < 128*768
    int nb = idx / FH, f = idx % FH;
    size_t base = (size_t)nb * GG;

    float gi = xw[base +        f] + b_ih[       f] + b_hh[       f];
    float gf = xw[base +  768 + f] + b_ih[ 768 + f] + b_hh[ 768 + f];
    float gg = xw[base + 1536 + f] + b_ih[1536 + f] + b_hh[1536 + f];
    float go = xw[base + 2304 + f] + b_ih[2304 + f] + b_hh[2304 + f];

    float cp = 0.f;
    if (t > 0) {
        gi += rec[base +        f];
        gf += rec[base +  768 + f];
        gg += rec[base + 1536 + f];
        go += rec[base + 2304 + f];
        cp  = c_state[idx];
    }

    float c  = sigm(gf) * cp + sigm(gi) * tanhf(gg);
    float hv = sigm(go) * tanhf(c);

    c_state[idx] = c;
    out[((size_t)nb * LT + t) * FH + f] = hv;

    if (t == LT - 1) {
        out[(size_t)NB * LT * FH + idx]            = hv;  // h_n
        out[(size_t)NB * LT * FH + NB * FH + idx]  = c;   // c_n
    }
}

// ---------------- launch ----------------
extern "C" void kernel_launch(void* const* d_in, const int* in_sizes, int n_in,
                              void* d_out, int out_size)
{
    const float* src     = (const float*)d_in[0];
    const float* W_pre   = (const float*)d_in[1];
    const float* b_pre   = (const float*)d_in[2];
    const float* W_gat   = (const float*)d_in[3];
    const float* att_src = (const float*)d_in[4];
    const float* att_dst = (const float*)d_in[5];
    const float* b_gat   = (const float*)d_in[6];
    const float* W_ih    = (const float*)d_in[7];
    const float* W_hh    = (const float*)d_in[8];
    const float* b_ih    = (const float*)d_in[9];
    const float* b_hh    = (const float*)d_in[10];
    float* out = (float*)d_out;

    float *Xp, *XWp, *Gp, *Cp;
    cudaGetSymbolAddress((void**)&Xp,  g_X);
    cudaGetSymbolAddress((void**)&XWp, g_XW);
    cudaGetSymbolAddress((void**)&Gp,  g_gates);
    cudaGetSymbolAddress((void**)&Cp,  g_c);

    // 1) GAT: 32768 graphs, 8 warps/block
    gat_kernel<<<BG / 8, 256>>>(src, W_pre, b_pre, W_gat, att_src, att_dst, b_gat, Xp);

    // 2) time-independent big GEMM: XW = X @ W_ih^T   [32768 x 3072], K=768
    sgemm_nt<128, 128, 8, 8, 8, 256><<<dim3(GG / 128, BG / 128), 256>>>(
        Xp, (size_t)FH, W_ih, (size_t)FH, XWp, (size_t)GG, FH);

    // 3) recurrence: per step, rec = h_{t-1} @ W_hh^T, then fused pointwise
    for (int t = 0; t < LT; t++) {
        if (t > 0) {
            // A = h_{t-1}: rows are batch n, A[m][k] = out[(m*256 + (t-1))*768 + k]
            sgemm_nt<32, 64, 16, 4, 4, 128><<<dim3(GG / 64, NB / 32), 128>>>(
                out + (size_t)(t - 1) * FH, (size_t)LT * FH,
                W_hh, (size_t)FH, Gp, (size_t)GG, FH);
        }
        lstm_point<<<(NB * FH) / 256, 256>>>(
            XWp + (size_t)t * NB * GG, Gp, b_ih, b_hh, out, Cp, t);
    }
}

// round 2
// speedup vs baseline: 1.2731x; 1.2731x over previous
#include <cuda_runtime.h>
#include <math.h>

// ---------------- problem constants ----------------
#define NB   128      // batch N
#define LT   256      // sequence length L
#define FH   768      // LSTM hidden (24*32)
#define GG   3072     // 4*768 gates
#define BG   (NB*LT)  // 32768 graphs
#define NBLK 128      // step-kernel blocks (6 features each)

// ---------------- scratch (device globals: allocation-free) ----------------
__device__ float  g_X [(size_t)BG * FH];     // GAT output, row r = t*128 + n
__device__ float  g_XW[(size_t)BG * GG];     // X @ W_ih^T, row r = t*128 + n
__device__ float  g_h [2 * NB * FH];         // ping-pong h, layout [feat][batch]
__device__ float  g_c [NB * FH];             // cell state, layout [feat][batch]
__device__ float2 g_Wd[(size_t)NBLK * FH * 24]; // permuted, pair-duplicated W_hh

__constant__ int c_par[24] = {-1,0,0,0,1,2,3,4,5,6,7,8,9,9,9,12,13,14,16,17,18,19,20,21};

__device__ __forceinline__ float sigm(float x) { return 1.f / (1.f + expf(-x)); }

__device__ __forceinline__ void fma2(unsigned long long &d,
                                     unsigned long long a,
                                     unsigned long long b) {
    asm("fma.rn.f32x2 %0, %1, %2, %0;" : "+l"(d) : "l"(a), "l"(b));
}

// ---------------- W_hh permute + pair-duplicate ----------------
// Block b owns rows r = g*6 + fi  <->  W_hh row (g*768 + b*6 + fi).
// Layout: g_Wd[b*768*24 + k*24 + r] = (w, w)
__global__ void prep_w(const float* __restrict__ W_hh) {
    size_t idx = (size_t)blockIdx.x * 256 + threadIdx.x;
    if (idx >= (size_t)NBLK * FH * 24) return;
    int r = (int)(idx % 24);
    int k = (int)((idx / 24) % FH);
    int b = (int)(idx / (24 * FH));
    int g = r / 6, fi = r % 6;
    float w = W_hh[(size_t)(g * FH + b * 6 + fi) * FH + k];
    g_Wd[idx] = make_float2(w, w);
}

// ---------------- GAT: one warp per graph ----------------
__global__ __launch_bounds__(256) void gat_kernel(
    const float* __restrict__ src,
    const float* __restrict__ W_pre, const float* __restrict__ b_pre,
    const float* __restrict__ W_gat,
    const float* __restrict__ att_src, const float* __restrict__ att_dst,
    const float* __restrict__ b_gat,
    float* __restrict__ X)
{
    __shared__ float Wg[32 * 32];
    __shared__ float xbuf[8][24][32];
    __shared__ float asd[8][24][2];

    int tid = threadIdx.x;
    for (int i = tid; i < 1024; i += 256) Wg[i] = W_gat[i];
    __syncthreads();

    int w = tid >> 5, h = tid & 31;
    int b = blockIdx.x * 8 + w;
    int n = b >> 8, l = b & 255;

    const float* s = src + (size_t)b * 72;
    float w0 = W_pre[h], w1 = W_pre[32 + h], w2 = W_pre[64 + h], bp = b_pre[h];

    #pragma unroll
    for (int j = 0; j < 24; j++) {
        float v = fmaf(s[j*3+2], w2, fmaf(s[j*3+1], w1, fmaf(s[j*3+0], w0, bp)));
        xbuf[w][j][h] = tanhf(v);
    }
    __syncwarp();

    float asrc = att_src[h], adst = att_dst[h];
    #pragma unroll
    for (int j = 0; j < 24; j++) {
        float acc = 0.f;
        #pragma unroll
        for (int k = 0; k < 32; k++) acc = fmaf(xbuf[w][j][k], Wg[k*32 + h], acc);
        float ps = acc * asrc, pd = acc * adst;
        #pragma unroll
        for (int o = 16; o > 0; o >>= 1) {
            ps += __shfl_xor_sync(0xffffffffu, ps, o);
            pd += __shfl_xor_sync(0xffffffffu, pd, o);
        }
        __syncwarp();
        xbuf[w][j][h] = acc;
        if (h == 0) { asd[w][j][0] = ps; asd[w][j][1] = pd; }
    }
    __syncwarp();

    float bg = b_gat[h];
    float* xrow = X + (size_t)(l * 128 + n) * FH;
    #pragma unroll
    for (int j = 0; j < 24; j++) {
        int p = c_par[j];
        float g;
        if (p < 0) {
            g = xbuf[w][j][h];
        } else {
            float ad = asd[w][j][1];
            float es = ad + asd[w][j][0];
            float ep = ad + asd[w][p][0];
            es = es > 0.f ? es : 0.2f * es;
            ep = ep > 0.f ? ep : 0.2f * ep;
            float m  = fmaxf(es, ep);
            float ws = expf(es - m), wp = expf(ep - m);
            float inv = 1.f / (ws + wp);
            g = (ws * xbuf[w][j][h] + wp * xbuf[w][p][h]) * inv;
        }
        xrow[j * 32 + h] = g + bg;
    }
}

// ---------------- big hoisted GEMM: C[m][n] = sum_k A[m*lda+k] * B[n*ldb+k] ----------------
template<int BM, int BN, int BK, int TM, int TN, int THREADS>
__global__ __launch_bounds__(THREADS) void sgemm_nt(
    const float* __restrict__ A, size_t lda,
    const float* __restrict__ B, size_t ldb,
    float* __restrict__ C, size_t ldc, int K)
{
    __shared__ float As[BK][BM + 1];
    __shared__ float Bs[BK][BN + 1];

    const int tid = threadIdx.x;
    const int m0 = blockIdx.y * BM;
    const int n0 = blockIdx.x * BN;
    const int CT = BN / TN;
    const int ty = tid / CT, tx = tid % CT;

    float acc[TM][TN];
    #pragma unroll
    for (int i = 0; i < TM; i++)
        #pragma unroll
        for (int j = 0; j < TN; j++) acc[i][j] = 0.f;

    for (int k0 = 0; k0 < K; k0 += BK) {
        #pragma unroll
        for (int i = tid; i < BM * BK; i += THREADS) {
            int r = i / BK, c = i % BK;
            As[c][r] = A[(size_t)(m0 + r) * lda + k0 + c];
        }
        #pragma unroll
        for (int i = tid; i < BN * BK; i += THREADS) {
            int r = i / BK, c = i % BK;
            Bs[c][r] = B[(size_t)(n0 + r) * ldb + k0 + c];
        }
        __syncthreads();

        #pragma unroll
        for (int kk = 0; kk < BK; kk++) {
            float af[TM], bf[TN];
            #pragma unroll
            for (int i = 0; i < TM; i++) af[i] = As[kk][ty * TM + i];
            #pragma unroll
            for (int j = 0; j < TN; j++) bf[j] = Bs[kk][tx * TN + j];
            #pragma unroll
            for (int i = 0; i < TM; i++)
                #pragma unroll
                for (int j = 0; j < TN; j++)
                    acc[i][j] = fmaf(af[i], bf[j], acc[i][j]);
        }
        __syncthreads();
    }

    #pragma unroll
    for (int i = 0; i < TM; i++) {
        float* crow = C + (size_t)(m0 + ty * TM + i) * ldc + n0 + tx * TN;
        #pragma unroll
        for (int j = 0; j < TN; j++) crow[j] = acc[i][j];
    }
}

// ---------------- fused LSTM step: rec GEMM (f32x2) + pointwise epilogue ----------------
// grid = 128 blocks; block b owns features [b*6, b*6+6) -> 24 gate rows.
// hin/hout/c layout: [feat][batch] (feature-major, coalesced everywhere).
__global__ __launch_bounds__(256) void lstm_step(
    const float* __restrict__ hin,
    float* __restrict__ hout,
    const float* __restrict__ xw,     // g_XW + t*128*3072, row-major [n][3072]
    const float* __restrict__ b_ih, const float* __restrict__ b_hh,
    float* __restrict__ out, float* __restrict__ c_state, int t)
{
    __shared__ float  As[32][132];     // [k][m]
    __shared__ float2 Ws[32 * 24];     // [k][r], pair-duplicated
    __shared__ float  Ct[24][130];     // gate tile for epilogue regroup
    __shared__ float  bias[24];

    const int tid = threadIdx.x;
    const int b   = blockIdx.x;

    if (tid < 24) {
        int g = tid / 6, fi = tid % 6;
        int gr = g * FH + b * 6 + fi;
        bias[tid] = b_ih[gr] + b_hh[gr];
    }

    const int tx = tid & 7;    // row triple: rows tx*3 .. tx*3+2
    const int ty = tid >> 3;   // batch quad: m = ty*4 .. ty*4+3

    unsigned long long acc[2][3];
    #pragma unroll
    for (int p = 0; p < 2; p++)
        #pragma unroll
        for (int j = 0; j < 3; j++) acc[p][j] = 0ull;

    if (t > 0) {
        const float2* wsrc = g_Wd + (size_t)b * (FH * 24);
        for (int kc = 0; kc < 24; kc++) {
            // stage h chunk: hin is [feat(=k)][m]; fully coalesced both sides
            #pragma unroll
            for (int i = 0; i < 4; i++) {
                int s  = tid + i * 256;        // 0..1023 float4 slots
                int k  = s >> 5;               // 0..31
                int m4 = s & 31;               // 0..31 (m quad)
                float4 v = *(const float4*)(hin + (size_t)(kc * 32 + k) * NB + m4 * 4);
                *(float4*)&As[k][m4 * 4] = v;
            }
            // stage W chunk: contiguous float2 copy
            #pragma unroll
            for (int i = 0; i < 3; i++)
                Ws[tid + i * 256] = wsrc[(size_t)kc * 768 + tid + i * 256];
            __syncthreads();

            #pragma unroll
            for (int kk = 0; kk < 32; kk++) {
                ulonglong2 a = *(const ulonglong2*)&As[kk][ty * 4];
                #pragma unroll
                for (int j = 0; j < 3; j++) {
                    unsigned long long w =
                        *(const unsigned long long*)&Ws[kk * 24 + tx * 3 + j];
                    fma2(acc[0][j], a.x, w);
                    fma2(acc[1][j], a.y, w);
                }
            }
            __syncthreads();
        }
    }

    // regroup gates through smem so each thread gets all 4 gates of a feature
    #pragma unroll
    for (int j = 0; j < 3; j++) {
        int r = tx * 3 + j;
        *(unsigned long long*)&Ct[r][ty * 4]     = acc[0][j];
        *(unsigned long long*)&Ct[r][ty * 4 + 2] = acc[1][j];
    }
    __syncthreads();

    // pointwise: 768 cells (128 batch x 6 features) / 256 threads = 3 each
    #pragma unroll
    for (int i = 0; i < 3; i++) {
        int e    = tid + i * 256;
        int m    = e & 127;
        int fi   = e >> 7;
        int feat = b * 6 + fi;
        const float* xwr = xw + (size_t)m * GG + feat;

        float gi = xwr[0]      + bias[0*6 + fi] + Ct[0*6 + fi][m];
        float gf = xwr[FH]     + bias[1*6 + fi] + Ct[1*6 + fi][m];
        float gg = xwr[2*FH]   + bias[2*6 + fi] + Ct[2*6 + fi][m];
        float go = xwr[3*FH]   + bias[3*6 + fi] + Ct[3*6 + fi][m];

        int   ci = feat * NB + m;           // feature-major state index
        float cp = (t > 0) ? c_state[ci] : 0.f;

        float c  = sigm(gf) * cp + sigm(gi) * tanhf(gg);
        float hv = sigm(go) * tanhf(c);

        c_state[ci] = c;
        hout[ci]    = hv;
        out[((size_t)m * LT + t) * FH + feat] = hv;

        if (t == LT - 1) {
            // h_n / c_n tails, batch-major [n][feat]
            out[(size_t)NB * LT * FH + (size_t)m * FH + feat]           = hv;
            out[(size_t)NB * LT * FH + NB * FH + (size_t)m * FH + feat] = c;
        }
    }
}

// ---------------- launch ----------------
extern "C" void kernel_launch(void* const* d_in, const int* in_sizes, int n_in,
                              void* d_out, int out_size)
{
    const float* src     = (const float*)d_in[0];
    const float* W_pre   = (const float*)d_in[1];
    const float* b_pre   = (const float*)d_in[2];
    const float* W_gat   = (const float*)d_in[3];
    const float* att_src = (const float*)d_in[4];
    const float* att_dst = (const float*)d_in[5];
    const float* b_gat   = (const float*)d_in[6];
    const float* W_ih    = (const float*)d_in[7];
    const float* W_hh    = (const float*)d_in[8];
    const float* b_ih    = (const float*)d_in[9];
    const float* b_hh    = (const float*)d_in[10];
    float* out = (float*)d_out;

    float *Xp, *XWp, *Hp, *Cp;
    cudaGetSymbolAddress((void**)&Xp,  g_X);
    cudaGetSymbolAddress((void**)&XWp, g_XW);
    cudaGetSymbolAddress((void**)&Hp,  g_h);
    cudaGetSymbolAddress((void**)&Cp,  g_c);

    // 0) permute + duplicate W_hh for the step kernel
    {
        size_t total = (size_t)NBLK * FH * 24;
        prep_w<<<(unsigned)((total + 255) / 256), 256>>>(W_hh);
    }

    // 1) GAT: 32768 graphs, 8 warps/block
    gat_kernel<<<BG / 8, 256>>>(src, W_pre, b_pre, W_gat, att_src, att_dst, b_gat, Xp);

    // 2) time-independent big GEMM: XW = X @ W_ih^T   [32768 x 3072], K=768
    sgemm_nt<128, 128, 8, 8, 8, 256><<<dim3(GG / 128, BG / 128), 256>>>(
        Xp, (size_t)FH, W_ih, (size_t)FH, XWp, (size_t)GG, FH);

    // 3) recurrence: 256 fused steps, h ping-pong (step t reads parity (t+1)&1, writes t&1)
    for (int t = 0; t < LT; t++) {
        lstm_step<<<NBLK, 256>>>(
            Hp + ((t + 1) & 1) * NB * FH,
            Hp + (t & 1) * NB * FH,
            XWp + (size_t)t * NB * GG,
            b_ih, b_hh, out, Cp, t);
    }
}

// round 4
// speedup vs baseline: 1.5725x; 1.2351x over previous
#include <cuda_runtime.h>
#include <cuda_bf16.h>
#include <math.h>
#include <stdint.h>

// ---------------- problem constants ----------------
#define NB   128
#define LT   256
#define FH   768
#define GG   3072
#define BG   (NB*LT)
#define NBLK 128

// packed-K GEMM config (K' = 3*FH for hi/lo compensation)
#define K3   (3*FH)          // 2304
#define BK   32              // bf16 per k-chunk (64 bytes)
#define NK   (K3/BK)         // 72 iterations
#define ROWB 80              // padded smem row stride (bytes): conflict-free ldmatrix
#define ATILE (128*ROWB)     // 10240 bytes
#define STAGEB (2*ATILE)     // A + B per stage

// ---------------- scratch (device globals) ----------------
__device__ __nv_bfloat16 g_Xp[(size_t)BG * K3];   // packed GAT output [ah, al, ah]
__device__ __nv_bfloat16 g_Wp[(size_t)GG * K3];   // packed W_ih       [bh, bh, bl]
__device__ float  g_XW[(size_t)BG * GG];          // X @ W_ih^T
__device__ float  g_h [2 * NB * FH];              // ping-pong h [feat][batch]
__device__ float  g_c [NB * FH];                  // cell state  [feat][batch]
__device__ float2 g_Wd[(size_t)NBLK * FH * 24];   // permuted pair-dup W_hh

__constant__ int c_par[24] = {-1,0,0,0,1,2,3,4,5,6,7,8,9,9,9,12,13,14,16,17,18,19,20,21};

__device__ __forceinline__ float sigm(float x) { return 1.f / (1.f + expf(-x)); }

__device__ __forceinline__ void fma2(unsigned long long &d,
                                     unsigned long long a,
                                     unsigned long long b) {
    asm("fma.rn.f32x2 %0, %1, %2, %0;" : "+l"(d) : "l"(a), "l"(b));
}

__device__ __forceinline__ uint32_t smem_u32(const void* p) {
    uint32_t a;
    asm("{ .reg .u64 t; cvta.to.shared.u64 t, %1; cvt.u32.u64 %0, t; }" : "=r"(a) : "l"(p));
    return a;
}

__device__ __forceinline__ void cp16(uint32_t s, const void* g) {
    asm volatile("cp.async.cg.shared.global [%0], [%1], 16;" :: "r"(s), "l"(g));
}

__device__ __forceinline__ void ldm_x4(uint32_t &r0, uint32_t &r1, uint32_t &r2,
                                       uint32_t &r3, uint32_t addr) {
    asm volatile("ldmatrix.sync.aligned.m8n8.x4.shared.b16 {%0,%1,%2,%3}, [%4];"
                 : "=r"(r0), "=r"(r1), "=r"(r2), "=r"(r3) : "r"(addr));
}

__device__ __forceinline__ void mma_bf16(float* d, const uint32_t* a,
                                         const uint32_t* b) {
    asm volatile(
        "mma.sync.aligned.m16n8k16.row.col.f32.bf16.bf16.f32 "
        "{%0,%1,%2,%3}, {%4,%5,%6,%7}, {%8,%9}, {%0,%1,%2,%3};"
        : "+f"(d[0]), "+f"(d[1]), "+f"(d[2]), "+f"(d[3])
        : "r"(a[0]), "r"(a[1]), "r"(a[2]), "r"(a[3]), "r"(b[0]), "r"(b[1]));
}

// ---------------- W_hh permute + pair-duplicate (step kernel) ----------------
__global__ void prep_w(const float* __restrict__ W_hh) {
    size_t idx = (size_t)blockIdx.x * 256 + threadIdx.x;
    if (idx >= (size_t)NBLK * FH * 24) return;
    int r = (int)(idx % 24);
    int k = (int)((idx / 24) % FH);
    int b = (int)(idx / (24 * FH));
    int g = r / 6, fi = r % 6;
    float w = W_hh[(size_t)(g * FH + b * 6 + fi) * FH + k];
    g_Wd[idx] = make_float2(w, w);
}

// ---------------- W_ih bf16 hi/lo pack: [bh, bh, bl] ----------------
__global__ void pack_w(const float* __restrict__ W, __nv_bfloat16* __restrict__ Wp) {
    int i = blockIdx.x * 256 + threadIdx.x;
    if (i >= GG * FH) return;
    int n = i / FH, k = i % FH;
    float w = W[i];
    __nv_bfloat16 wh = __float2bfloat16(w);
    __nv_bfloat16 wl = __float2bfloat16(w - __bfloat162float(wh));
    size_t o = (size_t)n * K3 + 3 * k;
    Wp[o] = wh; Wp[o + 1] = wh; Wp[o + 2] = wl;
}

// ---------------- GAT: one warp per graph, packs [ah, al, ah] ----------------
__global__ __launch_bounds__(256) void gat_kernel(
    const float* __restrict__ src,
    const float* __restrict__ W_pre, const float* __restrict__ b_pre,
    const float* __restrict__ W_gat,
    const float* __restrict__ att_src, const float* __restrict__ att_dst,
    const float* __restrict__ b_gat,
    __nv_bfloat16* __restrict__ Xp)
{
    __shared__ float Wg[32 * 32];
    __shared__ float xbuf[8][24][32];
    __shared__ float asd[8][24][2];

    int tid = threadIdx.x;
    for (int i = tid; i < 1024; i += 256) Wg[i] = W_gat[i];
    __syncthreads();

    int w = tid >> 5, h = tid & 31;
    int b = blockIdx.x * 8 + w;
    int n = b >> 8, l = b & 255;

    const float* s = src + (size_t)b * 72;
    float w0 = W_pre[h], w1 = W_pre[32 + h], w2 = W_pre[64 + h], bp = b_pre[h];

    #pragma unroll
    for (int j = 0; j < 24; j++) {
        float v = fmaf(s[j*3+2], w2, fmaf(s[j*3+1], w1, fmaf(s[j*3+0], w0, bp)));
        xbuf[w][j][h] = tanhf(v);
    }
    __syncwarp();

    float asrc = att_src[h], adst = att_dst[h];
    #pragma unroll
    for (int j = 0; j < 24; j++) {
        float acc = 0.f;
        #pragma unroll
        for (int k = 0; k < 32; k++) acc = fmaf(xbuf[w][j][k], Wg[k*32 + h], acc);
        float ps = acc * asrc, pd = acc * adst;
        #pragma unroll
        for (int o = 16; o > 0; o >>= 1) {
            ps += __shfl_xor_sync(0xffffffffu, ps, o);
            pd += __shfl_xor_sync(0xffffffffu, pd, o);
        }
        __syncwarp();
        xbuf[w][j][h] = acc;
        if (h == 0) { asd[w][j][0] = ps; asd[w][j][1] = pd; }
    }
    __syncwarp();

    float bg = b_gat[h];
    size_t rbase = (size_t)(l * 128 + n) * K3;
    #pragma unroll
    for (int j = 0; j < 24; j++) {
        int p = c_par[j];
        float g;
        if (p < 0) {
            g = xbuf[w][j][h];
        } else {
            float ad = asd[w][j][1];
            float es = ad + asd[w][j][0];
            float ep = ad + asd[w][p][0];
            es = es > 0.f ? es : 0.2f * es;
            ep = ep > 0.f ? ep : 0.2f * ep;
            float m  = fmaxf(es, ep);
            float ws = expf(es - m), wp = expf(ep - m);
            float inv = 1.f / (ws + wp);
            g = (ws * xbuf[w][j][h] + wp * xbuf[w][p][h]) * inv;
        }
        float v = g + bg;
        __nv_bfloat16 vh = __float2bfloat16(v);
        __nv_bfloat16 vl = __float2bfloat16(v - __bfloat162float(vh));
        size_t o = rbase + 3 * (j * 32 + h);
        Xp[o] = vh; Xp[o + 1] = vl; Xp[o + 2] = vh;
    }
}

// ---------------- bf16 mma.sync GEMM: C = A'(32768xK3) @ B'(3072xK3)^T ----------------
// Block 128x128, BK=32, double-buffered cp.async, 8 warps of 64x32.
__global__ __launch_bounds__(256, 2) void gemm_mma(
    const __nv_bfloat16* __restrict__ Ap,
    const __nv_bfloat16* __restrict__ Bp,
    float* __restrict__ C)
{
    __shared__ __align__(16) char sm[2 * STAGEB];

    const int tid  = threadIdx.x;
    const int lane = tid & 31;
    const int warp = tid >> 5;
    const int wm   = warp >> 2;         // 0..1  (64-row strip)
    const int wn   = warp & 3;          // 0..3  (32-col strip)
    const int n0   = blockIdx.x * 128;  // n fast -> Wp tile L2-resident
    const int m0   = blockIdx.y * 128;

    const uint32_t smb = smem_u32(sm);

    // cp.async staging map: 4 threads cover one 64B row
    const int ldRow = tid >> 2;
    const int ldSeg = tid & 3;
    const __nv_bfloat16* gA = Ap + (size_t)(m0 + ldRow) * K3 + ldSeg * 8;
    const __nv_bfloat16* gB = Bp + (size_t)(n0 + ldRow) * K3 + ldSeg * 8;
    const uint32_t stRow = ldRow * ROWB + ldSeg * 16;

    // ldmatrix base addresses (within a stage)
    const uint32_t aOff = (uint32_t)((wm * 64 + (lane & 7) + ((lane >> 3) & 1) * 8) * ROWB
                                     + ((lane >> 4) & 1) * 16);
    const uint32_t bOff = (uint32_t)(ATILE + (wn * 32 + (lane & 7) + ((lane >> 4) & 1) * 8) * ROWB
                                     + ((lane >> 3) & 1) * 16);

    float acc[4][4][4];
    #pragma unroll
    for (int i = 0; i < 4; i++)
        #pragma unroll
        for (int j = 0; j < 4; j++)
            #pragma unroll
            for (int q = 0; q < 4; q++) acc[i][j][q] = 0.f;

    // prologue: stage 0
    {
        uint32_t s0 = smb;
        #pragma unroll
        for (int i = 0; i < 2; i++) {
            cp16(s0 + stRow + i * 64 * ROWB,         gA + (size_t)i * 64 * K3);
            cp16(s0 + ATILE + stRow + i * 64 * ROWB, gB + (size_t)i * 64 * K3);
        }
        asm volatile("cp.async.commit_group;");
    }

    for (int kc = 0; kc < NK; kc++) {
        if (kc + 1 < NK) {
            uint32_t sn = smb + ((kc + 1) & 1) * STAGEB;
            int koff = (kc + 1) * BK;
            #pragma unroll
            for (int i = 0; i < 2; i++) {
                cp16(sn + stRow + i * 64 * ROWB,         gA + (size_t)i * 64 * K3 + koff);
                cp16(sn + ATILE + stRow + i * 64 * ROWB, gB + (size_t)i * 64 * K3 + koff);
            }
            asm volatile("cp.async.commit_group;");
            asm volatile("cp.async.wait_group 1;");
        } else {
            asm volatile("cp.async.wait_group 0;");
        }
        __syncthreads();

        const uint32_t soff = smb + (kc & 1) * STAGEB;
        #pragma unroll
        for (int ks = 0; ks < 2; ks++) {
            uint32_t a[4][4], bq[4][2];
            #pragma unroll
            for (int tm = 0; tm < 4; tm++)
                ldm_x4(a[tm][0], a[tm][1], a[tm][2], a[tm][3],
                       soff + aOff + tm * (16 * ROWB) + ks * 32);
            #pragma unroll
            for (int tb = 0; tb < 2; tb++) {
                uint32_t r0, r1, r2, r3;
                ldm_x4(r0, r1, r2, r3, soff + bOff + tb * (16 * ROWB) + ks * 32);
                bq[2*tb][0] = r0; bq[2*tb][1] = r1;
                bq[2*tb+1][0] = r2; bq[2*tb+1][1] = r3;
            }
            #pragma unroll
            for (int tm = 0; tm < 4; tm++)
                #pragma unroll
                for (int tn = 0; tn < 4; tn++)
                    mma_bf16(acc[tm][tn], a[tm], bq[tn]);
        }
        __syncthreads();
    }

    // epilogue
    #pragma unroll
    for (int tm = 0; tm < 4; tm++) {
        int row = m0 + wm * 64 + tm * 16 + (lane >> 2);
        #pragma unroll
        for (int tn = 0; tn < 4; tn++) {
            int col = n0 + wn * 32 + tn * 8 + (lane & 3) * 2;
            float* p = C + (size_t)row * GG + col;
            *(float2*)p                    = make_float2(acc[tm][tn][0], acc[tm][tn][1]);
            *(float2*)(p + (size_t)8 * GG) = make_float2(acc[tm][tn][2], acc[tm][tn][3]);
        }
    }
}

// ---------------- fused LSTM step (unchanged) ----------------
__global__ __launch_bounds__(256) void lstm_step(
    const float* __restrict__ hin,
    float* __restrict__ hout,
    const float* __restrict__ xw,
    const float* __restrict__ b_ih, const float* __restrict__ b_hh,
    float* __restrict__ out, float* __restrict__ c_state, int t)
{
    __shared__ float  As[32][132];
    __shared__ float2 Ws[32 * 24];
    __shared__ float  Ct[24][130];
    __shared__ float  bias[24];

    const int tid = threadIdx.x;
    const int b   = blockIdx.x;

    if (tid < 24) {
        int g = tid / 6, fi = tid % 6;
        int gr = g * FH + b * 6 + fi;
        bias[tid] = b_ih[gr] + b_hh[gr];
    }

    const int tx = tid & 7;
    const int ty = tid >> 3;

    unsigned long long acc[2][3];
    #pragma unroll
    for (int p = 0; p < 2; p++)
        #pragma unroll
        for (int j = 0; j < 3; j++) acc[p][j] = 0ull;

    if (t > 0) {
        const float2* wsrc = g_Wd + (size_t)b * (FH * 24);
        for (int kc = 0; kc < 24; kc++) {
            #pragma unroll
            for (int i = 0; i < 4; i++) {
                int s  = tid + i * 256;
                int k  = s >> 5;
                int m4 = s & 31;
                float4 v = *(const float4*)(hin + (size_t)(kc * 32 + k) * NB + m4 * 4);
                *(float4*)&As[k][m4 * 4] = v;
            }
            #pragma unroll
            for (int i = 0; i < 3; i++)
                Ws[tid + i * 256] = wsrc[(size_t)kc * 768 + tid + i * 256];
            __syncthreads();

            #pragma unroll
            for (int kk = 0; kk < 32; kk++) {
                ulonglong2 a = *(const ulonglong2*)&As[kk][ty * 4];
                #pragma unroll
                for (int j = 0; j < 3; j++) {
                    unsigned long long w =
                        *(const unsigned long long*)&Ws[kk * 24 + tx * 3 + j];
                    fma2(acc[0][j], a.x, w);
                    fma2(acc[1][j], a.y, w);
                }
            }
            __syncthreads();
        }
    }

    #pragma unroll
    for (int j = 0; j < 3; j++) {
        int r = tx * 3 + j;
        *(unsigned long long*)&Ct[r][ty * 4]     = acc[0][j];
        *(unsigned long long*)&Ct[r][ty * 4 + 2] = acc[1][j];
    }
    __syncthreads();

    #pragma unroll
    for (int i = 0; i < 3; i++) {
        int e    = tid + i * 256;
        int m    = e & 127;
        int fi   = e >> 7;
        int feat = b * 6 + fi;
        const float* xwr = xw + (size_t)m * GG + feat;

        float gi = xwr[0]      + bias[0*6 + fi] + Ct[0*6 + fi][m];
        float gf = xwr[FH]     + bias[1*6 + fi] + Ct[1*6 + fi][m];
        float gg = xwr[2*FH]   + bias[2*6 + fi] + Ct[2*6 + fi][m];
        float go = xwr[3*FH]   + bias[3*6 + fi] + Ct[3*6 + fi][m];

        int   ci = feat * NB + m;
        float cp = (t > 0) ? c_state[ci] : 0.f;

        float c  = sigm(gf) * cp + sigm(gi) * tanhf(gg);
        float hv = sigm(go) * tanhf(c);

        c_state[ci] = c;
        hout[ci]    = hv;
        out[((size_t)m * LT + t) * FH + feat] = hv;

        if (t == LT - 1) {
            out[(size_t)NB * LT * FH + (size_t)m * FH + feat]           = hv;
            out[(size_t)NB * LT * FH + NB * FH + (size_t)m * FH + feat] = c;
        }
    }
}

// ---------------- launch ----------------
extern "C" void kernel_launch(void* const* d_in, const int* in_sizes, int n_in,
                              void* d_out, int out_size)
{
    const float* src     = (const float*)d_in[0];
    const float* W_pre   = (const float*)d_in[1];
    const float* b_pre   = (const float*)d_in[2];
    const float* W_gat   = (const float*)d_in[3];
    const float* att_src = (const float*)d_in[4];
    const float* att_dst = (const float*)d_in[5];
    const float* b_gat   = (const float*)d_in[6];
    const float* W_ih    = (const float*)d_in[7];
    const float* W_hh    = (const float*)d_in[8];
    const float* b_ih    = (const float*)d_in[9];
    const float* b_hh    = (const float*)d_in[10];
    float* out = (float*)d_out;

    __nv_bfloat16 *Xp, *Wp;
    float *XWp, *Hp, *Cp;
    cudaGetSymbolAddress((void**)&Xp,  g_Xp);
    cudaGetSymbolAddress((void**)&Wp,  g_Wp);
    cudaGetSymbolAddress((void**)&XWp, g_XW);
    cudaGetSymbolAddress((void**)&Hp,  g_h);
    cudaGetSymbolAddress((void**)&Cp,  g_c);

    // 0) weight prep
    prep_w<<<(unsigned)(((size_t)NBLK * FH * 24 + 255) / 256), 256>>>(W_hh);
    pack_w<<<(GG * FH + 255) / 256, 256>>>(W_ih, Wp);

    // 1) GAT -> packed bf16 X
    gat_kernel<<<BG / 8, 256>>>(src, W_pre, b_pre, W_gat, att_src, att_dst, b_gat, Xp);

    // 2) big GEMM on tensor cores (mma.sync bf16, compensated)
    gemm_mma<<<dim3(GG / 128, BG / 128), 256>>>(Xp, Wp, XWp);

    // 3) recurrence
    for (int t = 0; t < LT; t++) {
        lstm_step<<<NBLK, 256>>>(
            Hp + ((t + 1) & 1) * NB * FH,
            Hp + (t & 1) * NB * FH,
            XWp + (size_t)t * NB * GG,
            b_ih, b_hh, out, Cp, t);
    }
}

// round 5
// speedup vs baseline: 1.6497x; 1.0491x over previous
#include <cuda_runtime.h>
#include <cuda_fp16.h>
#include <math.h>
#include <stdint.h>

// ---------------- problem constants ----------------
#define NB   128
#define LT   256
#define FH   768
#define GG   3072
#define BG   (NB*LT)
#define NBLK 128

// packed-K GEMM config (K' = 2*FH: fp16 hi/lo compensation on A side)
#define K2   (2*FH)          // 1536
#define BK   32              // fp16 per k-chunk (64 bytes)
#define NK2  (K2/BK)         // 48 chunks
#define ROWB 80              // padded smem row stride (bytes)
#define ATILE (128*ROWB)     // 10240 bytes
#define STAGEB (2*ATILE)     // A + B per stage = 20480
#define NSTAGE 4
#define GEMM_SMEM (NSTAGE*STAGEB)   // 81920

// ---------------- scratch (device globals) ----------------
__device__ __half g_Xp[(size_t)BG * K2];   // packed GAT output [ah | al]
__device__ __half g_Wp[(size_t)GG * K2];   // packed W_ih       [bh | bh]
__device__ float  g_XW[(size_t)BG * GG];
__device__ float  g_h [2 * NB * FH];
__device__ float  g_c [NB * FH];
__device__ float2 g_Wd[(size_t)NBLK * FH * 24];

__constant__ int c_par[24] = {-1,0,0,0,1,2,3,4,5,6,7,8,9,9,9,12,13,14,16,17,18,19,20,21};

__device__ __forceinline__ float sigm(float x) { return 1.f / (1.f + expf(-x)); }

__device__ __forceinline__ void fma2(unsigned long long &d,
                                     unsigned long long a,
                                     unsigned long long b) {
    asm("fma.rn.f32x2 %0, %1, %2, %0;" : "+l"(d) : "l"(a), "l"(b));
}

__device__ __forceinline__ uint32_t smem_u32(const void* p) {
    uint32_t a;
    asm("{ .reg .u64 t; cvta.to.shared.u64 t, %1; cvt.u32.u64 %0, t; }" : "=r"(a) : "l"(p));
    return a;
}

__device__ __forceinline__ void cp16(uint32_t s, const void* g) {
    asm volatile("cp.async.cg.shared.global [%0], [%1], 16;" :: "r"(s), "l"(g));
}

__device__ __forceinline__ void ldm_x4(uint32_t &r0, uint32_t &r1, uint32_t &r2,
                                       uint32_t &r3, uint32_t addr) {
    asm volatile("ldmatrix.sync.aligned.m8n8.x4.shared.b16 {%0,%1,%2,%3}, [%4];"
                 : "=r"(r0), "=r"(r1), "=r"(r2), "=r"(r3) : "r"(addr));
}

__device__ __forceinline__ void mma_f16(float* d, const uint32_t* a,
                                        const uint32_t* b) {
    asm volatile(
        "mma.sync.aligned.m16n8k16.row.col.f32.f16.f16.f32 "
        "{%0,%1,%2,%3}, {%4,%5,%6,%7}, {%8,%9}, {%0,%1,%2,%3};"
        : "+f"(d[0]), "+f"(d[1]), "+f"(d[2]), "+f"(d[3])
        : "r"(a[0]), "r"(a[1]), "r"(a[2]), "r"(a[3]), "r"(b[0]), "r"(b[1]));
}

// ---------------- W_hh permute + pair-duplicate (step kernel) ----------------
__global__ void prep_w(const float* __restrict__ W_hh) {
    size_t idx = (size_t)blockIdx.x * 256 + threadIdx.x;
    if (idx >= (size_t)NBLK * FH * 24) return;
    int r = (int)(idx % 24);
    int k = (int)((idx / 24) % FH);
    int b = (int)(idx / (24 * FH));
    int g = r / 6, fi = r % 6;
    float w = W_hh[(size_t)(g * FH + b * 6 + fi) * FH + k];
    g_Wd[idx] = make_float2(w, w);
}

// ---------------- W_ih fp16 pack: [bh | bh] ----------------
__global__ void pack_w(const float* __restrict__ W, __half* __restrict__ Wp) {
    int i = blockIdx.x * 256 + threadIdx.x;
    if (i >= GG * FH) return;
    int n = i / FH, k = i % FH;
    __half wh = __float2half(W[i]);
    size_t o = (size_t)n * K2 + k;
    Wp[o] = wh; Wp[o + FH] = wh;
}

// ---------------- GAT: one warp per graph, packs [ah | al] ----------------
__global__ __launch_bounds__(256) void gat_kernel(
    const float* __restrict__ src,
    const float* __restrict__ W_pre, const float* __restrict__ b_pre,
    const float* __restrict__ W_gat,
    const float* __restrict__ att_src, const float* __restrict__ att_dst,
    const float* __restrict__ b_gat,
    __half* __restrict__ Xp)
{
    __shared__ float Wg[32 * 32];
    __shared__ float xbuf[8][24][32];
    __shared__ float asd[8][24][2];

    int tid = threadIdx.x;
    for (int i = tid; i < 1024; i += 256) Wg[i] = W_gat[i];
    __syncthreads();

    int w = tid >> 5, h = tid & 31;
    int b = blockIdx.x * 8 + w;
    int n = b >> 8, l = b & 255;

    const float* s = src + (size_t)b * 72;
    float w0 = W_pre[h], w1 = W_pre[32 + h], w2 = W_pre[64 + h], bp = b_pre[h];

    #pragma unroll
    for (int j = 0; j < 24; j++) {
        float v = fmaf(s[j*3+2], w2, fmaf(s[j*3+1], w1, fmaf(s[j*3+0], w0, bp)));
        xbuf[w][j][h] = tanhf(v);
    }
    __syncwarp();

    float asrc = att_src[h], adst = att_dst[h];
    #pragma unroll
    for (int j = 0; j < 24; j++) {
        float acc = 0.f;
        #pragma unroll
        for (int k = 0; k < 32; k++) acc = fmaf(xbuf[w][j][k], Wg[k*32 + h], acc);
        float ps = acc * asrc, pd = acc * adst;
        #pragma unroll
        for (int o = 16; o > 0; o >>= 1) {
            ps += __shfl_xor_sync(0xffffffffu, ps, o);
            pd += __shfl_xor_sync(0xffffffffu, pd, o);
        }
        __syncwarp();
        xbuf[w][j][h] = acc;
        if (h == 0) { asd[w][j][0] = ps; asd[w][j][1] = pd; }
    }
    __syncwarp();

    float bg = b_gat[h];
    size_t rbase = (size_t)(l * 128 + n) * K2;
    #pragma unroll
    for (int j = 0; j < 24; j++) {
        int p = c_par[j];
        float g;
        if (p < 0) {
            g = xbuf[w][j][h];
        } else {
            float ad = asd[w][j][1];
            float es = ad + asd[w][j][0];
            float ep = ad + asd[w][p][0];
            es = es > 0.f ? es : 0.2f * es;
            ep = ep > 0.f ? ep : 0.2f * ep;
            float m  = fmaxf(es, ep);
            float ws = expf(es - m), wp = expf(ep - m);
            float inv = 1.f / (ws + wp);
            g = (ws * xbuf[w][j][h] + wp * xbuf[w][p][h]) * inv;
        }
        float v = g + bg;
        __half vh = __float2half(v);
        size_t o = rbase + j * 32 + h;
        Xp[o]      = vh;
        Xp[o + FH] = __float2half(v - __half2float(vh));
    }
}

// ---------------- fp16 mma.sync GEMM, 4-stage pipeline ----------------
// C = A'(32768 x K2) @ B'(3072 x K2)^T ; block 128x128, 8 warps of 64x32.
__global__ __launch_bounds__(256, 2) void gemm_mma(
    const __half* __restrict__ Ap,
    const __half* __restrict__ Bp,
    float* __restrict__ C)
{
    extern __shared__ __align__(16) char sm[];

    const int tid  = threadIdx.x;
    const int lane = tid & 31;
    const int warp = tid >> 5;
    const int wm   = warp >> 2;
    const int wn   = warp & 3;
    const int n0   = blockIdx.x * 128;   // n fast -> Wp tile L2-resident
    const int m0   = blockIdx.y * 128;

    const uint32_t smb = smem_u32(sm);

    const int ldRow = tid >> 2;
    const int ldSeg = tid & 3;
    const __half* gA = Ap + (size_t)(m0 + ldRow) * K2 + ldSeg * 8;
    const __half* gB = Bp + (size_t)(n0 + ldRow) * K2 + ldSeg * 8;
    const uint32_t stRow = ldRow * ROWB + ldSeg * 16;

    const uint32_t aOff = (uint32_t)((wm * 64 + (lane & 7) + ((lane >> 3) & 1) * 8) * ROWB
                                     + ((lane >> 4) & 1) * 16);
    const uint32_t bOff = (uint32_t)(ATILE + (wn * 32 + (lane & 7) + ((lane >> 4) & 1) * 8) * ROWB
                                     + ((lane >> 3) & 1) * 16);

    float acc[4][4][4];
    #pragma unroll
    for (int i = 0; i < 4; i++)
        #pragma unroll
        for (int j = 0; j < 4; j++)
            #pragma unroll
            for (int q = 0; q < 4; q++) acc[i][j][q] = 0.f;

    // prologue: stages 0,1,2
    #pragma unroll
    for (int pc = 0; pc < NSTAGE - 1; pc++) {
        uint32_t sb = smb + pc * STAGEB;
        int ko = pc * BK;
        #pragma unroll
        for (int i = 0; i < 2; i++) {
            cp16(sb + stRow + i * 64 * ROWB,         gA + (size_t)i * 64 * K2 + ko);
            cp16(sb + ATILE + stRow + i * 64 * ROWB, gB + (size_t)i * 64 * K2 + ko);
        }
        asm volatile("cp.async.commit_group;");
    }

    for (int kc = 0; kc < NK2; kc++) {
        asm volatile("cp.async.wait_group %0;" :: "n"(NSTAGE - 2));
        __syncthreads();

        // prefetch chunk kc+3 into stage (kc+3)%4 (safe: all warps past barrier)
        if (kc + NSTAGE - 1 < NK2) {
            uint32_t sb = smb + ((kc + NSTAGE - 1) & (NSTAGE - 1)) * STAGEB;
            int ko = (kc + NSTAGE - 1) * BK;
            #pragma unroll
            for (int i = 0; i < 2; i++) {
                cp16(sb + stRow + i * 64 * ROWB,         gA + (size_t)i * 64 * K2 + ko);
                cp16(sb + ATILE + stRow + i * 64 * ROWB, gB + (size_t)i * 64 * K2 + ko);
            }
        }
        asm volatile("cp.async.commit_group;");

        const uint32_t soff = smb + (kc & (NSTAGE - 1)) * STAGEB;
        #pragma unroll
        for (int ks = 0; ks < 2; ks++) {
            uint32_t a[4][4], bq[4][2];
            #pragma unroll
            for (int tm = 0; tm < 4; tm++)
                ldm_x4(a[tm][0], a[tm][1], a[tm][2], a[tm][3],
                       soff + aOff + tm * (16 * ROWB) + ks * 32);
            #pragma unroll
            for (int tb = 0; tb < 2; tb++) {
                uint32_t r0, r1, r2, r3;
                ldm_x4(r0, r1, r2, r3, soff + bOff + tb * (16 * ROWB) + ks * 32);
                bq[2*tb][0] = r0; bq[2*tb][1] = r1;
                bq[2*tb+1][0] = r2; bq[2*tb+1][1] = r3;
            }
            #pragma unroll
            for (int tm = 0; tm < 4; tm++)
                #pragma unroll
                for (int tn = 0; tn < 4; tn++)
                    mma_f16(acc[tm][tn], a[tm], bq[tn]);
        }
    }

    // epilogue
    #pragma unroll
    for (int tm = 0; tm < 4; tm++) {
        int row = m0 + wm * 64 + tm * 16 + (lane >> 2);
        #pragma unroll
        for (int tn = 0; tn < 4; tn++) {
            int col = n0 + wn * 32 + tn * 8 + (lane & 3) * 2;
            float* p = C + (size_t)row * GG + col;
            *(float2*)p                    = make_float2(acc[tm][tn][0], acc[tm][tn][1]);
            *(float2*)(p + (size_t)8 * GG) = make_float2(acc[tm][tn][2], acc[tm][tn][3]);
        }
    }
}

// ---------------- fused LSTM step (unchanged) ----------------
__global__ __launch_bounds__(256) void lstm_step(
    const float* __restrict__ hin,
    float* __restrict__ hout,
    const float* __restrict__ xw,
    const float* __restrict__ b_ih, const float* __restrict__ b_hh,
    float* __restrict__ out, float* __restrict__ c_state, int t)
{
    __shared__ float  As[32][132];
    __shared__ float2 Ws[32 * 24];
    __shared__ float  Ct[24][130];
    __shared__ float  bias[24];

    const int tid = threadIdx.x;
    const int b   = blockIdx.x;

    if (tid < 24) {
        int g = tid / 6, fi = tid % 6;
        int gr = g * FH + b * 6 + fi;
        bias[tid] = b_ih[gr] + b_hh[gr];
    }

    const int tx = tid & 7;
    const int ty = tid >> 3;

    unsigned long long acc[2][3];
    #pragma unroll
    for (int p = 0; p < 2; p++)
        #pragma unroll
        for (int j = 0; j < 3; j++) acc[p][j] = 0ull;

    if (t > 0) {
        const float2* wsrc = g_Wd + (size_t)b * (FH * 24);
        for (int kc = 0; kc < 24; kc++) {
            #pragma unroll
            for (int i = 0; i < 4; i++) {
                int s  = tid + i * 256;
                int k  = s >> 5;
                int m4 = s & 31;
                float4 v = *(const float4*)(hin + (size_t)(kc * 32 + k) * NB + m4 * 4);
                *(float4*)&As[k][m4 * 4] = v;
            }
            #pragma unroll
            for (int i = 0; i < 3; i++)
                Ws[tid + i * 256] = wsrc[(size_t)kc * 768 + tid + i * 256];
            __syncthreads();

            #pragma unroll
            for (int kk = 0; kk < 32; kk++) {
                ulonglong2 a = *(const ulonglong2*)&As[kk][ty * 4];
                #pragma unroll
                for (int j = 0; j < 3; j++) {
                    unsigned long long w =
                        *(const unsigned long long*)&Ws[kk * 24 + tx * 3 + j];
                    fma2(acc[0][j], a.x, w);
                    fma2(acc[1][j], a.y, w);
                }
            }
            __syncthreads();
        }
    }

    #pragma unroll
    for (int j = 0; j < 3; j++) {
        int r = tx * 3 + j;
        *(unsigned long long*)&Ct[r][ty * 4]     = acc[0][j];
        *(unsigned long long*)&Ct[r][ty * 4 + 2] = acc[1][j];
    }
    __syncthreads();

    #pragma unroll
    for (int i = 0; i < 3; i++) {
        int e    = tid + i * 256;
        int m    = e & 127;
        int fi   = e >> 7;
        int feat = b * 6 + fi;
        const float* xwr = xw + (size_t)m * GG + feat;

        float gi = xwr[0]      + bias[0*6 + fi] + Ct[0*6 + fi][m];
        float gf = xwr[FH]     + bias[1*6 + fi] + Ct[1*6 + fi][m];
        float gg = xwr[2*FH]   + bias[2*6 + fi] + Ct[2*6 + fi][m];
        float go = xwr[3*FH]   + bias[3*6 + fi] + Ct[3*6 + fi][m];

        int   ci = feat * NB + m;
        float cp = (t > 0) ? c_state[ci] : 0.f;

        float c  = sigm(gf) * cp + sigm(gi) * tanhf(gg);
        float hv = sigm(go) * tanhf(c);

        c_state[ci] = c;
        hout[ci]    = hv;
        out[((size_t)m * LT + t) * FH + feat] = hv;

        if (t == LT - 1) {
            out[(size_t)NB * LT * FH + (size_t)m * FH + feat]           = hv;
            out[(size_t)NB * LT * FH + NB * FH + (size_t)m * FH + feat] = c;
        }
    }
}

// ---------------- launch ----------------
extern "C" void kernel_launch(void* const* d_in, const int* in_sizes, int n_in,
                              void* d_out, int out_size)
{
    const float* src     = (const float*)d_in[0];
    const float* W_pre   = (const float*)d_in[1];
    const float* b_pre   = (const float*)d_in[2];
    const float* W_gat   = (const float*)d_in[3];
    const float* att_src = (const float*)d_in[4];
    const float* att_dst = (const float*)d_in[5];
    const float* b_gat   = (const float*)d_in[6];
    const float* W_ih    = (const float*)d_in[7];
    const float* W_hh    = (const float*)d_in[8];
    const float* b_ih    = (const float*)d_in[9];
    const float* b_hh    = (const float*)d_in[10];
    float* out = (float*)d_out;

    __half *Xp, *Wp;
    float *XWp, *Hp, *Cp;
    cudaGetSymbolAddress((void**)&Xp,  g_Xp);
    cudaGetSymbolAddress((void**)&Wp,  g_Wp);
    cudaGetSymbolAddress((void**)&XWp, g_XW);
    cudaGetSymbolAddress((void**)&Hp,  g_h);
    cudaGetSymbolAddress((void**)&Cp,  g_c);

    cudaFuncSetAttribute(gemm_mma, cudaFuncAttributeMaxDynamicSharedMemorySize,
                         GEMM_SMEM);

    // 0) weight prep
    prep_w<<<(unsigned)(((size_t)NBLK * FH * 24 + 255) / 256), 256>>>(W_hh);
    pack_w<<<(GG * FH + 255) / 256, 256>>>(W_ih, Wp);

    // 1) GAT -> packed fp16 X
    gat_kernel<<<BG / 8, 256>>>(src, W_pre, b_pre, W_gat, att_src, att_dst, b_gat, Xp);

    // 2) big GEMM on tensor cores (mma.sync fp16, 2-term compensation)
    gemm_mma<<<dim3(GG / 128, BG / 128), 256, GEMM_SMEM>>>(Xp, Wp, XWp);

    // 3) recurrence
    for (int t = 0; t < LT; t++) {
        lstm_step<<<NBLK, 256>>>(
            Hp + ((t + 1) & 1) * NB * FH,
            Hp + (t & 1) * NB * FH,
            XWp + (size_t)t * NB * GG,
            b_ih, b_hh, out, Cp, t);
    }
}

// round 6
// speedup vs baseline: 2.3067x; 1.3982x over previous
#include <cuda_runtime.h>
#include <cuda_fp16.h>
#include <math.h>
#include <stdint.h>

// ---------------- problem constants ----------------
#define NB   128
#define LT   256
#define FH   768
#define GG   3072
#define BG   (NB*LT)

// ---- big hoisted GEMM (fp16 2-term), unchanged from round 5 ----
#define K2   (2*FH)          // 1536
#define BK   32
#define NK2  (K2/BK)         // 48
#define ROWB 80
#define ATILE (128*ROWB)
#define STAGEB (2*ATILE)
#define NSTAGE 4
#define GEMM_SMEM (NSTAGE*STAGEB)   // 81920

// ---- recurrent tensor step (fp16 3-term) ----
#define KR    2304           // 3*FH
#define RBK   64             // k per chunk
#define RNCH  (KR/RBK)       // 36
#define RROW  144            // smem row stride bytes (64 fp16 + 16B pad)
#define RA_BY (128*RROW)     // 18432
#define RW_BY (32*RROW)      // 4608
#define RSTG  (RA_BY+RW_BY)  // 23040
#define RNST  3
#define RSMEM (RNST*RSTG)    // 69120
#define NRB   96             // blocks = 3072/32

// ---------------- scratch (device globals) ----------------
__device__ __half g_Xp [(size_t)BG * K2];     // packed GAT out [ah | al]
__device__ __half g_Wp [(size_t)GG * K2];     // packed W_ih    [bh | bh]
__device__ __half g_Whp[(size_t)GG * KR];     // packed+permuted W_hh [wh|wh|wl]
__device__ __half g_hp [2][(size_t)NB * KR];  // ping-pong packed h [hh|hl|hh]
__device__ float  g_XW [(size_t)BG * GG];
__device__ float  g_c  [GG / 4 * NB];         // cell state [feat][batch] (768*128)

__constant__ int c_par[24] = {-1,0,0,0,1,2,3,4,5,6,7,8,9,9,9,12,13,14,16,17,18,19,20,21};

__device__ __forceinline__ float sigm(float x) { return 1.f / (1.f + expf(-x)); }

__device__ __forceinline__ uint32_t smem_u32(const void* p) {
    uint32_t a;
    asm("{ .reg .u64 t; cvta.to.shared.u64 t, %1; cvt.u32.u64 %0, t; }" : "=r"(a) : "l"(p));
    return a;
}

__device__ __forceinline__ void cp16(uint32_t s, const void* g) {
    asm volatile("cp.async.cg.shared.global [%0], [%1], 16;" :: "r"(s), "l"(g));
}

__device__ __forceinline__ void ldm_x4(uint32_t &r0, uint32_t &r1, uint32_t &r2,
                                       uint32_t &r3, uint32_t addr) {
    asm volatile("ldmatrix.sync.aligned.m8n8.x4.shared.b16 {%0,%1,%2,%3}, [%4];"
                 : "=r"(r0), "=r"(r1), "=r"(r2), "=r"(r3) : "r"(addr));
}

__device__ __forceinline__ void mma_f16(float* d, const uint32_t* a,
                                        const uint32_t* b) {
    asm volatile(
        "mma.sync.aligned.m16n8k16.row.col.f32.f16.f16.f32 "
        "{%0,%1,%2,%3}, {%4,%5,%6,%7}, {%8,%9}, {%0,%1,%2,%3};"
        : "+f"(d[0]), "+f"(d[1]), "+f"(d[2]), "+f"(d[3])
        : "r"(a[0]), "r"(a[1]), "r"(a[2]), "r"(a[3]), "r"(b[0]), "r"(b[1]));
}

// ---------------- W_ih fp16 pack: [bh | bh] ----------------
__global__ void pack_w(const float* __restrict__ W, __half* __restrict__ Wp) {
    int i = blockIdx.x * 256 + threadIdx.x;
    if (i >= GG * FH) return;
    int n = i / FH, k = i % FH;
    __half wh = __float2half(W[i]);
    size_t o = (size_t)n * K2 + k;
    Wp[o] = wh; Wp[o + FH] = wh;
}

// ---------------- W_hh permute + 3-term pack ----------------
// Block b owns local rows r = g*8 + fi <-> W_hh row (g*768 + b*8 + fi).
// Layout: g_Whp[(b*32 + r)*KR + k], k segments = [wh | wh | wl].
__global__ void pack_whh(const float* __restrict__ W) {
    size_t idx = (size_t)blockIdx.x * 256 + threadIdx.x;
    if (idx >= (size_t)GG * KR) return;
    int k   = (int)(idx % KR);
    int row = (int)(idx / KR);       // b*32 + r
    int b = row >> 5, r = row & 31;
    int g = r >> 3, fi = r & 7;
    int seg = k / FH, kk = k % FH;
    float w = W[(size_t)(g * FH + b * 8 + fi) * FH + kk];
    __half wh = __float2half(w);
    g_Whp[idx] = (seg < 2) ? wh : __float2half(w - __half2float(wh));
}

// ---------------- GAT: one warp per graph, packs [ah | al] ----------------
__global__ __launch_bounds__(256) void gat_kernel(
    const float* __restrict__ src,
    const float* __restrict__ W_pre, const float* __restrict__ b_pre,
    const float* __restrict__ W_gat,
    const float* __restrict__ att_src, const float* __restrict__ att_dst,
    const float* __restrict__ b_gat,
    __half* __restrict__ Xp)
{
    __shared__ float Wg[32 * 32];
    __shared__ float xbuf[8][24][32];
    __shared__ float asd[8][24][2];

    int tid = threadIdx.x;
    for (int i = tid; i < 1024; i += 256) Wg[i] = W_gat[i];
    __syncthreads();

    int w = tid >> 5, h = tid & 31;
    int b = blockIdx.x * 8 + w;
    int n = b >> 8, l = b & 255;

    const float* s = src + (size_t)b * 72;
    float w0 = W_pre[h], w1 = W_pre[32 + h], w2 = W_pre[64 + h], bp = b_pre[h];

    #pragma unroll
    for (int j = 0; j < 24; j++) {
        float v = fmaf(s[j*3+2], w2, fmaf(s[j*3+1], w1, fmaf(s[j*3+0], w0, bp)));
        xbuf[w][j][h] = tanhf(v);
    }
    __syncwarp();

    float asrc = att_src[h], adst = att_dst[h];
    #pragma unroll
    for (int j = 0; j < 24; j++) {
        float acc = 0.f;
        #pragma unroll
        for (int k = 0; k < 32; k++) acc = fmaf(xbuf[w][j][k], Wg[k*32 + h], acc);
        float ps = acc * asrc, pd = acc * adst;
        #pragma unroll
        for (int o = 16; o > 0; o >>= 1) {
            ps += __shfl_xor_sync(0xffffffffu, ps, o);
            pd += __shfl_xor_sync(0xffffffffu, pd, o);
        }
        __syncwarp();
        xbuf[w][j][h] = acc;
        if (h == 0) { asd[w][j][0] = ps; asd[w][j][1] = pd; }
    }
    __syncwarp();

    float bg = b_gat[h];
    size_t rbase = (size_t)(l * 128 + n) * K2;
    #pragma unroll
    for (int j = 0; j < 24; j++) {
        int p = c_par[j];
        float g;
        if (p < 0) {
            g = xbuf[w][j][h];
        } else {
            float ad = asd[w][j][1];
            float es = ad + asd[w][j][0];
            float ep = ad + asd[w][p][0];
            es = es > 0.f ? es : 0.2f * es;
            ep = ep > 0.f ? ep : 0.2f * ep;
            float m  = fmaxf(es, ep);
            float ws = expf(es - m), wp = expf(ep - m);
            float inv = 1.f / (ws + wp);
            g = (ws * xbuf[w][j][h] + wp * xbuf[w][p][h]) * inv;
        }
        float v = g + bg;
        __half vh = __float2half(v);
        size_t o = rbase + j * 32 + h;
        Xp[o]      = vh;
        Xp[o + FH] = __float2half(v - __half2float(vh));
    }
}

// ---------------- big fp16 mma GEMM (unchanged, 0.89ms proven) ----------------
__global__ __launch_bounds__(256, 2) void gemm_mma(
    const __half* __restrict__ Ap,
    const __half* __restrict__ Bp,
    float* __restrict__ C)
{
    extern __shared__ __align__(16) char sm[];

    const int tid  = threadIdx.x;
    const int lane = tid & 31;
    const int warp = tid >> 5;
    const int wm   = warp >> 2;
    const int wn   = warp & 3;
    const int n0   = blockIdx.x * 128;
    const int m0   = blockIdx.y * 128;

    const uint32_t smb = smem_u32(sm);

    const int ldRow = tid >> 2;
    const int ldSeg = tid & 3;
    const __half* gA = Ap + (size_t)(m0 + ldRow) * K2 + ldSeg * 8;
    const __half* gB = Bp + (size_t)(n0 + ldRow) * K2 + ldSeg * 8;
    const uint32_t stRow = ldRow * ROWB + ldSeg * 16;

    const uint32_t aOff = (uint32_t)((wm * 64 + (lane & 7) + ((lane >> 3) & 1) * 8) * ROWB
                                     + ((lane >> 4) & 1) * 16);
    const uint32_t bOff = (uint32_t)(ATILE + (wn * 32 + (lane & 7) + ((lane >> 4) & 1) * 8) * ROWB
                                     + ((lane >> 3) & 1) * 16);

    float acc[4][4][4];
    #pragma unroll
    for (int i = 0; i < 4; i++)
        #pragma unroll
        for (int j = 0; j < 4; j++)
            #pragma unroll
            for (int q = 0; q < 4; q++) acc[i][j][q] = 0.f;

    #pragma unroll
    for (int pc = 0; pc < NSTAGE - 1; pc++) {
        uint32_t sb = smb + pc * STAGEB;
        int ko = pc * BK;
        #pragma unroll
        for (int i = 0; i < 2; i++) {
            cp16(sb + stRow + i * 64 * ROWB,         gA + (size_t)i * 64 * K2 + ko);
            cp16(sb + ATILE + stRow + i * 64 * ROWB, gB + (size_t)i * 64 * K2 + ko);
        }
        asm volatile("cp.async.commit_group;");
    }

    for (int kc = 0; kc < NK2; kc++) {
        asm volatile("cp.async.wait_group %0;" :: "n"(NSTAGE - 2));
        __syncthreads();

        if (kc + NSTAGE - 1 < NK2) {
            uint32_t sb = smb + ((kc + NSTAGE - 1) & (NSTAGE - 1)) * STAGEB;
            int ko = (kc + NSTAGE - 1) * BK;
            #pragma unroll
            for (int i = 0; i < 2; i++) {
                cp16(sb + stRow + i * 64 * ROWB,         gA + (size_t)i * 64 * K2 + ko);
                cp16(sb + ATILE + stRow + i * 64 * ROWB, gB + (size_t)i * 64 * K2 + ko);
            }
        }
        asm volatile("cp.async.commit_group;");

        const uint32_t soff = smb + (kc & (NSTAGE - 1)) * STAGEB;
        #pragma unroll
        for (int ks = 0; ks < 2; ks++) {
            uint32_t a[4][4], bq[4][2];
            #pragma unroll
            for (int tm = 0; tm < 4; tm++)
                ldm_x4(a[tm][0], a[tm][1], a[tm][2], a[tm][3],
                       soff + aOff + tm * (16 * ROWB) + ks * 32);
            #pragma unroll
            for (int tb = 0; tb < 2; tb++) {
                uint32_t r0, r1, r2, r3;
                ldm_x4(r0, r1, r2, r3, soff + bOff + tb * (16 * ROWB) + ks * 32);
                bq[2*tb][0] = r0; bq[2*tb][1] = r1;
                bq[2*tb+1][0] = r2; bq[2*tb+1][1] = r3;
            }
            #pragma unroll
            for (int tm = 0; tm < 4; tm++)
                #pragma unroll
                for (int tn = 0; tn < 4; tn++)
                    mma_f16(acc[tm][tn], a[tm], bq[tn]);
        }
    }

    #pragma unroll
    for (int tm = 0; tm < 4; tm++) {
        int row = m0 + wm * 64 + tm * 16 + (lane >> 2);
        #pragma unroll
        for (int tn = 0; tn < 4; tn++) {
            int col = n0 + wn * 32 + tn * 8 + (lane & 3) * 2;
            float* p = C + (size_t)row * GG + col;
            *(float2*)p                    = make_float2(acc[tm][tn][0], acc[tm][tn][1]);
            *(float2*)(p + (size_t)8 * GG) = make_float2(acc[tm][tn][2], acc[tm][tn][3]);
        }
    }
}

// ---------------- tensor-core fused LSTM step ----------------
// Block b: N-slice = 32 gate rows (8 features x 4 gates, permuted in g_Whp).
// GEMM: M=128, N=32, K=KR (3-term fp16). Epilogue: gates->smem, fused pointwise.
__global__ __launch_bounds__(256) void lstm_step_tc(
    const __half* __restrict__ hin,       // packed h (read parity)
    __half* __restrict__ houtp,           // packed h (write parity)
    const float* __restrict__ xw,         // g_XW + t*128*3072
    const float* __restrict__ bih, const float* __restrict__ bhh,
    float* __restrict__ out, float* __restrict__ c_state, int t)
{
    extern __shared__ __align__(16) char sm[];
    const uint32_t smb = smem_u32(sm);

    const int tid  = threadIdx.x;
    const int lane = tid & 31;
    const int warp = tid >> 5;
    const int wm   = warp >> 1;          // 0..3: 32-row m strip
    const int wn   = warp & 1;           // 0..1: 16-row n strip
    const int b    = blockIdx.x;

    float acc[2][2][4];
    #pragma unroll
    for (int i = 0; i < 2; i++)
        #pragma unroll
        for (int j = 0; j < 2; j++)
            #pragma unroll
            for (int q = 0; q < 4; q++) acc[i][j][q] = 0.f;

    if (t > 0) {
        const __half* Wb = g_Whp + (size_t)b * 32 * KR;

        // cp.async maps: A 1024 slots (4/thread), W 256 slots (1/thread)
        const int wRow = tid >> 3, wSeg = tid & 7;       // W: row 0..31, seg 0..7
        const uint32_t wSt = RA_BY + wRow * RROW + wSeg * 16;
        const __half* gW = Wb + (size_t)wRow * KR + wSeg * 8;

        const uint32_t aOff = (uint32_t)((wm * 32 + (lane & 15)) * RROW
                                         + ((lane >> 4) & 1) * 16);
        const uint32_t bOff = (uint32_t)(RA_BY
                              + (wn * 16 + (lane & 7) + ((lane >> 4) & 1) * 8) * RROW
                              + ((lane >> 3) & 1) * 16);

        // prologue: stages 0,1
        #pragma unroll
        for (int pc = 0; pc < RNST - 1; pc++) {
            uint32_t sb = smb + pc * RSTG;
            int ko = pc * RBK;
            #pragma unroll
            for (int i = 0; i < 4; i++) {
                int slot = tid + i * 256;
                int row = slot >> 3, seg = slot & 7;
                cp16(sb + row * RROW + seg * 16,
                     hin + (size_t)row * KR + ko + seg * 8);
            }
            cp16(sb + wSt, gW + ko);
            asm volatile("cp.async.commit_group;");
        }

        for (int kc = 0; kc < RNCH; kc++) {
            asm volatile("cp.async.wait_group %0;" :: "n"(RNST - 2));
            __syncthreads();

            if (kc + RNST - 1 < RNCH) {
                uint32_t sb = smb + ((kc + RNST - 1) % RNST) * RSTG;
                int ko = (kc + RNST - 1) * RBK;
                #pragma unroll
                for (int i = 0; i < 4; i++) {
                    int slot = tid + i * 256;
                    int row = slot >> 3, seg = slot & 7;
                    cp16(sb + row * RROW + seg * 16,
                         hin + (size_t)row * KR + ko + seg * 8);
                }
                cp16(sb + wSt, gW + ko);
            }
            asm volatile("cp.async.commit_group;");

            const uint32_t soff = smb + (kc % RNST) * RSTG;
            #pragma unroll
            for (int ks = 0; ks < RBK / 16; ks++) {
                uint32_t a[2][4], bq[2][2];
                #pragma unroll
                for (int tm = 0; tm < 2; tm++)
                    ldm_x4(a[tm][0], a[tm][1], a[tm][2], a[tm][3],
                           soff + aOff + tm * (16 * RROW) + ks * 32);
                {
                    uint32_t r0, r1, r2, r3;
                    ldm_x4(r0, r1, r2, r3, soff + bOff + ks * 32);
                    bq[0][0] = r0; bq[0][1] = r1;
                    bq[1][0] = r2; bq[1][1] = r3;
                }
                #pragma unroll
                for (int tm = 0; tm < 2; tm++)
                    #pragma unroll
                    for (int tn = 0; tn < 2; tn++)
                        mma_f16(acc[tm][tn], a[tm], bq[tn]);
            }
        }
        asm volatile("cp.async.wait_group 0;");
    }
    __syncthreads();

    // gate tile overlay: Gt[32 n][132 m] fp32 (aliases stage smem)
    float* Gt = (float*)sm;
    #pragma unroll
    for (int tm = 0; tm < 2; tm++) {
        int m = wm * 32 + tm * 16 + (lane >> 2);
        #pragma unroll
        for (int tn = 0; tn < 2; tn++) {
            int n = wn * 16 + tn * 8 + (lane & 3) * 2;
            Gt[n * 132 + m]           = acc[tm][tn][0];
            Gt[(n + 1) * 132 + m]     = acc[tm][tn][1];
            Gt[n * 132 + m + 8]       = acc[tm][tn][2];
            Gt[(n + 1) * 132 + m + 8] = acc[tm][tn][3];
        }
    }
    __syncthreads();

    // fused pointwise: 8 features x 128 batch = 1024 cells, 4/thread
    #pragma unroll
    for (int i = 0; i < 4; i++) {
        int e  = tid + i * 256;
        int m  = e & 127;
        int fi = e >> 7;                 // 0..7
        int feat = b * 8 + fi;
        const float* xwr = xw + (size_t)m * GG + feat;

        float gi = Gt[(0*8 + fi) * 132 + m] + xwr[0]    + bih[feat]          + bhh[feat];
        float gf = Gt[(1*8 + fi) * 132 + m] + xwr[FH]   + bih[FH + feat]     + bhh[FH + feat];
        float gg = Gt[(2*8 + fi) * 132 + m] + xwr[2*FH] + bih[2*FH + feat]   + bhh[2*FH + feat];
        float go = Gt[(3*8 + fi) * 132 + m] + xwr[3*FH] + bih[3*FH + feat]   + bhh[3*FH + feat];

        int   ci = feat * NB + m;
        float cp = (t > 0) ? c_state[ci] : 0.f;

        float c  = sigm(gf) * cp + sigm(gi) * tanhf(gg);
        float hv = sigm(go) * tanhf(c);

        c_state[ci] = c;
        out[((size_t)m * LT + t) * FH + feat] = hv;

        __half hh = __float2half(hv);
        __half hl = __float2half(hv - __half2float(hh));
        size_t hb = (size_t)m * KR + feat;
        houtp[hb]          = hh;
        houtp[hb + FH]     = hl;
        houtp[hb + 2*FH]   = hh;

        if (t == LT - 1) {
            out[(size_t)NB * LT * FH + (size_t)m * FH + feat]           = hv;
            out[(size_t)NB * LT * FH + NB * FH + (size_t)m * FH + feat] = c;
        }
    }
}

// ---------------- launch ----------------
extern "C" void kernel_launch(void* const* d_in, const int* in_sizes, int n_in,
                              void* d_out, int out_size)
{
    const float* src     = (const float*)d_in[0];
    const float* W_pre   = (const float*)d_in[1];
    const float* b_pre   = (const float*)d_in[2];
    const float* W_gat   = (const float*)d_in[3];
    const float* att_src = (const float*)d_in[4];
    const float* att_dst = (const float*)d_in[5];
    const float* b_gat   = (const float*)d_in[6];
    const float* W_ih    = (const float*)d_in[7];
    const float* W_hh    = (const float*)d_in[8];
    const float* b_ih    = (const float*)d_in[9];
    const float* b_hh    = (const float*)d_in[10];
    float* out = (float*)d_out;

    __half *Xp, *Wp, *Hp;
    float *XWp, *Cp;
    cudaGetSymbolAddress((void**)&Xp,  g_Xp);
    cudaGetSymbolAddress((void**)&Wp,  g_Wp);
    cudaGetSymbolAddress((void**)&Hp,  g_hp);
    cudaGetSymbolAddress((void**)&XWp, g_XW);
    cudaGetSymbolAddress((void**)&Cp,  g_c);

    cudaFuncSetAttribute(gemm_mma, cudaFuncAttributeMaxDynamicSharedMemorySize,
                         GEMM_SMEM);
    cudaFuncSetAttribute(lstm_step_tc, cudaFuncAttributeMaxDynamicSharedMemorySize,
                         RSMEM);

    // 0) weight prep
    pack_w<<<(GG * FH + 255) / 256, 256>>>(W_ih, Wp);
    pack_whh<<<(unsigned)(((size_t)GG * KR + 255) / 256), 256>>>(W_hh);

    // 1) GAT -> packed fp16 X
    gat_kernel<<<BG / 8, 256>>>(src, W_pre, b_pre, W_gat, att_src, att_dst, b_gat, Xp);

    // 2) big GEMM on tensor cores
    gemm_mma<<<dim3(GG / 128, BG / 128), 256, GEMM_SMEM>>>(Xp, Wp, XWp);

    // 3) recurrence on tensor cores (ping-pong packed h)
    const size_t HPAR = (size_t)NB * KR;
    for (int t = 0; t < LT; t++) {
        lstm_step_tc<<<NRB, 256, RSMEM>>>(
            Hp + ((t + 1) & 1) * HPAR,
            Hp + (t & 1) * HPAR,
            XWp + (size_t)t * NB * GG,
            b_ih, b_hh, out, Cp, t);
    }
}

// round 7
// speedup vs baseline: 2.4883x; 1.0787x over previous
#include <cuda_runtime.h>
#include <cuda_fp16.h>
#include <math.h>
#include <stdint.h>

// ---------------- problem constants ----------------
#define NB   128
#define LT   256
#define FH   768
#define GG   3072
#define BG   (NB*LT)

// ---- big hoisted GEMM (fp16 2-term) ----
#define K2   (2*FH)          // 1536
#define BK   32
#define NK2  (K2/BK)         // 48
#define ROWB 80
#define ATILE (128*ROWB)
#define STAGEB (2*ATILE)
#define NSTAGE 4
#define GEMM_SMEM (NSTAGE*STAGEB)   // 81920

// ---- persistent recurrent kernel (fp16 3-term) ----
#define KR    2304           // 3*FH
#define RBK   64             // k per chunk
#define RNCH  (KR/RBK)       // 36
#define RROW  144            // smem row stride bytes (64 fp16 + 16B pad)
#define RA_BY (128*RROW)     // 18432 per A stage
#define RNST  3
#define WCHB  (32*RROW)      // 4608 per W chunk
#define WBASE (RNST*RA_BY)   // 55296
#define PSMEM (WBASE + RNCH*WCHB)   // 55296+165888 = 221184
#define NRB   96             // blocks = 3072/32

// ---------------- scratch (device globals) ----------------
__device__ __half g_Xp [(size_t)BG * K2];     // packed GAT out [ah | al]
__device__ __half g_Wp [(size_t)GG * K2];     // packed W_ih    [bh | bh]
__device__ __half g_Whp[(size_t)GG * KR];     // packed+permuted W_hh [wh|wh|wl]
__device__ __half g_hp [2][(size_t)NB * KR];  // ping-pong packed h [hh|hl|hh]
__device__ float  g_XW [(size_t)BG * GG];
__device__ float  g_c  [FH * NB];             // cell state [feat][batch]
__device__ unsigned g_ctr;                    // grid barrier counter

__constant__ int c_par[24] = {-1,0,0,0,1,2,3,4,5,6,7,8,9,9,9,12,13,14,16,17,18,19,20,21};

__device__ __forceinline__ float sigm(float x) { return 1.f / (1.f + expf(-x)); }

__device__ __forceinline__ uint32_t smem_u32(const void* p) {
    uint32_t a;
    asm("{ .reg .u64 t; cvta.to.shared.u64 t, %1; cvt.u32.u64 %0, t; }" : "=r"(a) : "l"(p));
    return a;
}

__device__ __forceinline__ void cp16(uint32_t s, const void* g) {
    asm volatile("cp.async.cg.shared.global [%0], [%1], 16;" :: "r"(s), "l"(g));
}

__device__ __forceinline__ void ldm_x4(uint32_t &r0, uint32_t &r1, uint32_t &r2,
                                       uint32_t &r3, uint32_t addr) {
    asm volatile("ldmatrix.sync.aligned.m8n8.x4.shared.b16 {%0,%1,%2,%3}, [%4];"
                 : "=r"(r0), "=r"(r1), "=r"(r2), "=r"(r3) : "r"(addr));
}

__device__ __forceinline__ void mma_f16(float* d, const uint32_t* a,
                                        const uint32_t* b) {
    asm volatile(
        "mma.sync.aligned.m16n8k16.row.col.f32.f16.f16.f32 "
        "{%0,%1,%2,%3}, {%4,%5,%6,%7}, {%8,%9}, {%0,%1,%2,%3};"
        : "+f"(d[0]), "+f"(d[1]), "+f"(d[2]), "+f"(d[3])
        : "r"(a[0]), "r"(a[1]), "r"(a[2]), "r"(a[3]), "r"(b[0]), "r"(b[1]));
}

// ---------------- small prep kernels ----------------
__global__ void reset_ctr() { g_ctr = 0u; }

__global__ void pack_w(const float* __restrict__ W, __half* __restrict__ Wp) {
    int i = blockIdx.x * 256 + threadIdx.x;
    if (i >= GG * FH) return;
    int n = i / FH, k = i % FH;
    __half wh = __float2half(W[i]);
    size_t o = (size_t)n * K2 + k;
    Wp[o] = wh; Wp[o + FH] = wh;
}

// Block b owns local rows r = g*8 + fi <-> W_hh row (g*768 + b*8 + fi)
__global__ void pack_whh(const float* __restrict__ W) {
    size_t idx = (size_t)blockIdx.x * 256 + threadIdx.x;
    if (idx >= (size_t)GG * KR) return;
    int k   = (int)(idx % KR);
    int row = (int)(idx / KR);
    int b = row >> 5, r = row & 31;
    int g = r >> 3, fi = r & 7;
    int seg = k / FH, kk = k % FH;
    float w = W[(size_t)(g * FH + b * 8 + fi) * FH + kk];
    __half wh = __float2half(w);
    g_Whp[idx] = (seg < 2) ? wh : __float2half(w - __half2float(wh));
}

// ---------------- GAT: one warp per graph, packs [ah | al] ----------------
__global__ __launch_bounds__(256) void gat_kernel(
    const float* __restrict__ src,
    const float* __restrict__ W_pre, const float* __restrict__ b_pre,
    const float* __restrict__ W_gat,
    const float* __restrict__ att_src, const float* __restrict__ att_dst,
    const float* __restrict__ b_gat,
    __half* __restrict__ Xp)
{
    __shared__ float Wg[32 * 32];
    __shared__ float xbuf[8][24][32];
    __shared__ float asd[8][24][2];

    int tid = threadIdx.x;
    for (int i = tid; i < 1024; i += 256) Wg[i] = W_gat[i];
    __syncthreads();

    int w = tid >> 5, h = tid & 31;
    int b = blockIdx.x * 8 + w;
    int n = b >> 8, l = b & 255;

    const float* s = src + (size_t)b * 72;
    float w0 = W_pre[h], w1 = W_pre[32 + h], w2 = W_pre[64 + h], bp = b_pre[h];

    #pragma unroll
    for (int j = 0; j < 24; j++) {
        float v = fmaf(s[j*3+2], w2, fmaf(s[j*3+1], w1, fmaf(s[j*3+0], w0, bp)));
        xbuf[w][j][h] = tanhf(v);
    }
    __syncwarp();

    float asrc = att_src[h], adst = att_dst[h];
    #pragma unroll
    for (int j = 0; j < 24; j++) {
        float acc = 0.f;
        #pragma unroll
        for (int k = 0; k < 32; k++) acc = fmaf(xbuf[w][j][k], Wg[k*32 + h], acc);
        float ps = acc * asrc, pd = acc * adst;
        #pragma unroll
        for (int o = 16; o > 0; o >>= 1) {
            ps += __shfl_xor_sync(0xffffffffu, ps, o);
            pd += __shfl_xor_sync(0xffffffffu, pd, o);
        }
        __syncwarp();
        xbuf[w][j][h] = acc;
        if (h == 0) { asd[w][j][0] = ps; asd[w][j][1] = pd; }
    }
    __syncwarp();

    float bg = b_gat[h];
    size_t rbase = (size_t)(l * 128 + n) * K2;
    #pragma unroll
    for (int j = 0; j < 24; j++) {
        int p = c_par[j];
        float g;
        if (p < 0) {
            g = xbuf[w][j][h];
        } else {
            float ad = asd[w][j][1];
            float es = ad + asd[w][j][0];
            float ep = ad + asd[w][p][0];
            es = es > 0.f ? es : 0.2f * es;
            ep = ep > 0.f ? ep : 0.2f * ep;
            float m  = fmaxf(es, ep);
            float ws = expf(es - m), wp = expf(ep - m);
            float inv = 1.f / (ws + wp);
            g = (ws * xbuf[w][j][h] + wp * xbuf[w][p][h]) * inv;
        }
        float v = g + bg;
        __half vh = __float2half(v);
        size_t o = rbase + j * 32 + h;
        Xp[o]      = vh;
        Xp[o + FH] = __float2half(v - __half2float(vh));
    }
}

// ---------------- big fp16 mma GEMM (proven 0.89ms) ----------------
__global__ __launch_bounds__(256, 2) void gemm_mma(
    const __half* __restrict__ Ap,
    const __half* __restrict__ Bp,
    float* __restrict__ C)
{
    extern __shared__ __align__(16) char sm[];

    const int tid  = threadIdx.x;
    const int lane = tid & 31;
    const int warp = tid >> 5;
    const int wm   = warp >> 2;
    const int wn   = warp & 3;
    const int n0   = blockIdx.x * 128;
    const int m0   = blockIdx.y * 128;

    const uint32_t smb = smem_u32(sm);

    const int ldRow = tid >> 2;
    const int ldSeg = tid & 3;
    const __half* gA = Ap + (size_t)(m0 + ldRow) * K2 + ldSeg * 8;
    const __half* gB = Bp + (size_t)(n0 + ldRow) * K2 + ldSeg * 8;
    const uint32_t stRow = ldRow * ROWB + ldSeg * 16;

    const uint32_t aOff = (uint32_t)((wm * 64 + (lane & 7) + ((lane >> 3) & 1) * 8) * ROWB
                                     + ((lane >> 4) & 1) * 16);
    const uint32_t bOff = (uint32_t)(ATILE + (wn * 32 + (lane & 7) + ((lane >> 4) & 1) * 8) * ROWB
                                     + ((lane >> 3) & 1) * 16);

    float acc[4][4][4];
    #pragma unroll
    for (int i = 0; i < 4; i++)
        #pragma unroll
        for (int j = 0; j < 4; j++)
            #pragma unroll
            for (int q = 0; q < 4; q++) acc[i][j][q] = 0.f;

    #pragma unroll
    for (int pc = 0; pc < NSTAGE - 1; pc++) {
        uint32_t sb = smb + pc * STAGEB;
        int ko = pc * BK;
        #pragma unroll
        for (int i = 0; i < 2; i++) {
            cp16(sb + stRow + i * 64 * ROWB,         gA + (size_t)i * 64 * K2 + ko);
            cp16(sb + ATILE + stRow + i * 64 * ROWB, gB + (size_t)i * 64 * K2 + ko);
        }
        asm volatile("cp.async.commit_group;");
    }

    for (int kc = 0; kc < NK2; kc++) {
        asm volatile("cp.async.wait_group %0;" :: "n"(NSTAGE - 2));
        __syncthreads();

        if (kc + NSTAGE - 1 < NK2) {
            uint32_t sb = smb + ((kc + NSTAGE - 1) & (NSTAGE - 1)) * STAGEB;
            int ko = (kc + NSTAGE - 1) * BK;
            #pragma unroll
            for (int i = 0; i < 2; i++) {
                cp16(sb + stRow + i * 64 * ROWB,         gA + (size_t)i * 64 * K2 + ko);
                cp16(sb + ATILE + stRow + i * 64 * ROWB, gB + (size_t)i * 64 * K2 + ko);
            }
        }
        asm volatile("cp.async.commit_group;");

        const uint32_t soff = smb + (kc & (NSTAGE - 1)) * STAGEB;
        #pragma unroll
        for (int ks = 0; ks < 2; ks++) {
            uint32_t a[4][4], bq[4][2];
            #pragma unroll
            for (int tm = 0; tm < 4; tm++)
                ldm_x4(a[tm][0], a[tm][1], a[tm][2], a[tm][3],
                       soff + aOff + tm * (16 * ROWB) + ks * 32);
            #pragma unroll
            for (int tb = 0; tb < 2; tb++) {
                uint32_t r0, r1, r2, r3;
                ldm_x4(r0, r1, r2, r3, soff + bOff + tb * (16 * ROWB) + ks * 32);
                bq[2*tb][0] = r0; bq[2*tb][1] = r1;
                bq[2*tb+1][0] = r2; bq[2*tb+1][1] = r3;
            }
            #pragma unroll
            for (int tm = 0; tm < 4; tm++)
                #pragma unroll
                for (int tn = 0; tn < 4; tn++)
                    mma_f16(acc[tm][tn], a[tm], bq[tn]);
        }
    }

    #pragma unroll
    for (int tm = 0; tm < 4; tm++) {
        int row = m0 + wm * 64 + tm * 16 + (lane >> 2);
        #pragma unroll
        for (int tn = 0; tn < 4; tn++) {
            int col = n0 + wn * 32 + tn * 8 + (lane & 3) * 2;
            float* p = C + (size_t)row * GG + col;
            *(float2*)p                    = make_float2(acc[tm][tn][0], acc[tm][tn][1]);
            *(float2*)(p + (size_t)8 * GG) = make_float2(acc[tm][tn][2], acc[tm][tn][3]);
        }
    }
}

// ---------------- persistent LSTM: all 256 steps in one launch ----------------
// 96 co-resident blocks; block b holds W_hh slice (32 gate rows) in smem for
// the whole sequence. Grid barrier = monotonic atomic counter + spin.
__global__ __launch_bounds__(256) void lstm_persist(
    const float* __restrict__ xwbase,
    const float* __restrict__ bih, const float* __restrict__ bhh,
    float* __restrict__ out, float* __restrict__ c_state)
{
    extern __shared__ __align__(16) char sm[];
    const uint32_t smb = smem_u32(sm);

    const int tid  = threadIdx.x;
    const int lane = tid & 31;
    const int warp = tid >> 5;
    const int wm   = warp >> 1;          // 0..3: 32-row m strip
    const int wn   = warp & 1;           // 0..1: 16-row n strip
    const int b    = blockIdx.x;

    // ---- one-time: resident W slice into smem (36 chunks x 32 rows x 64 halfs)
    {
        const __half* Wb = g_Whp + (size_t)b * 32 * KR;
        for (int i = tid; i < RNCH * 256; i += 256) {
            int chunk = i >> 8;
            int rem   = i & 255;
            int row   = rem >> 3, seg = rem & 7;
            cp16(smb + WBASE + chunk * WCHB + row * RROW + seg * 16,
                 Wb + (size_t)row * KR + chunk * RBK + seg * 8);
        }
        asm volatile("cp.async.commit_group;");
        asm volatile("cp.async.wait_group 0;");
    }

    // ---- per-block bias (32 gate rows)
    __shared__ float bias_s[32];
    if (tid < 32) {
        int g = tid >> 3, fi = tid & 7;
        int gr = g * FH + b * 8 + fi;
        bias_s[tid] = bih[gr] + bhh[gr];
    }
    __syncthreads();

    const uint32_t aOff = (uint32_t)((wm * 32 + (lane & 15)) * RROW
                                     + ((lane >> 4) & 1) * 16);
    const uint32_t bOffW = (uint32_t)((wn * 16 + (lane & 7) + ((lane >> 4) & 1) * 8) * RROW
                                      + ((lane >> 3) & 1) * 16);

    unsigned* ctr = &g_ctr;

    for (int t = 0; t < LT; t++) {
        const __half* hin   = g_hp[(t + 1) & 1];
        __half*       houtp = g_hp[t & 1];
        const float*  xw    = xwbase + (size_t)t * NB * GG;

        float acc[2][2][4];
        #pragma unroll
        for (int i = 0; i < 2; i++)
            #pragma unroll
            for (int j = 0; j < 2; j++)
                #pragma unroll
                for (int q = 0; q < 4; q++) acc[i][j][q] = 0.f;

        if (t > 0) {
            // prologue: stage A chunks 0,1
            #pragma unroll
            for (int pc = 0; pc < RNST - 1; pc++) {
                uint32_t sb = smb + pc * RA_BY;
                int ko = pc * RBK;
                #pragma unroll
                for (int i = 0; i < 4; i++) {
                    int slot = tid + i * 256;
                    int row = slot >> 3, seg = slot & 7;
                    cp16(sb + row * RROW + seg * 16,
                         hin + (size_t)row * KR + ko + seg * 8);
                }
                asm volatile("cp.async.commit_group;");
            }

            for (int kc = 0; kc < RNCH; kc++) {
                asm volatile("cp.async.wait_group %0;" :: "n"(RNST - 2));
                __syncthreads();

                if (kc + RNST - 1 < RNCH) {
                    uint32_t sb = smb + ((kc + RNST - 1) % RNST) * RA_BY;
                    int ko = (kc + RNST - 1) * RBK;
                    #pragma unroll
                    for (int i = 0; i < 4; i++) {
                        int slot = tid + i * 256;
                        int row = slot >> 3, seg = slot & 7;
                        cp16(sb + row * RROW + seg * 16,
                             hin + (size_t)row * KR + ko + seg * 8);
                    }
                }
                asm volatile("cp.async.commit_group;");

                const uint32_t soff = smb + (kc % RNST) * RA_BY;
                const uint32_t woff = smb + WBASE + kc * WCHB;
                #pragma unroll
                for (int ks = 0; ks < RBK / 16; ks++) {
                    uint32_t a[2][4], bq[2][2];
                    #pragma unroll
                    for (int tm = 0; tm < 2; tm++)
                        ldm_x4(a[tm][0], a[tm][1], a[tm][2], a[tm][3],
                               soff + aOff + tm * (16 * RROW) + ks * 32);
                    {
                        uint32_t r0, r1, r2, r3;
                        ldm_x4(r0, r1, r2, r3, woff + bOffW + ks * 32);
                        bq[0][0] = r0; bq[0][1] = r1;
                        bq[1][0] = r2; bq[1][1] = r3;
                    }
                    #pragma unroll
                    for (int tm = 0; tm < 2; tm++)
                        #pragma unroll
                        for (int tn = 0; tn < 2; tn++)
                            mma_f16(acc[tm][tn], a[tm], bq[tn]);
                }
            }
            asm volatile("cp.async.wait_group 0;");
        }
        __syncthreads();

        // gate tile overlay in A-stage region: Gt[32 n][132 m] fp32
        float* Gt = (float*)sm;
        #pragma unroll
        for (int tm = 0; tm < 2; tm++) {
            int m = wm * 32 + tm * 16 + (lane >> 2);
            #pragma unroll
            for (int tn = 0; tn < 2; tn++) {
                int n = wn * 16 + tn * 8 + (lane & 3) * 2;
                Gt[n * 132 + m]           = acc[tm][tn][0];
                Gt[(n + 1) * 132 + m]     = acc[tm][tn][1];
                Gt[n * 132 + m + 8]       = acc[tm][tn][2];
                Gt[(n + 1) * 132 + m + 8] = acc[tm][tn][3];
            }
        }
        __syncthreads();

        // fused pointwise: 8 features x 128 batch, 4 cells/thread
        #pragma unroll
        for (int i = 0; i < 4; i++) {
            int e  = tid + i * 256;
            int m  = e & 127;
            int fi = e >> 7;
            int feat = b * 8 + fi;
            const float* xwr = xw + (size_t)m * GG + feat;

            float gi = Gt[(0*8 + fi) * 132 + m] + xwr[0]    + bias_s[0*8 + fi];
            float gf = Gt[(1*8 + fi) * 132 + m] + xwr[FH]   + bias_s[1*8 + fi];
            float gg = Gt[(2*8 + fi) * 132 + m] + xwr[2*FH] + bias_s[2*8 + fi];
            float go = Gt[(3*8 + fi) * 132 + m] + xwr[3*FH] + bias_s[3*8 + fi];

            int   ci = feat * NB + m;
            float cp = (t > 0) ? c_state[ci] : 0.f;

            float c  = sigm(gf) * cp + sigm(gi) * tanhf(gg);
            float hv = sigm(go) * tanhf(c);

            c_state[ci] = c;
            out[((size_t)m * LT + t) * FH + feat] = hv;

            __half hh = __float2half(hv);
            __half hl = __float2half(hv - __half2float(hh));
            size_t hb = (size_t)m * KR + feat;
            houtp[hb]        = hh;
            houtp[hb + FH]   = hl;
            houtp[hb + 2*FH] = hh;

            if (t == LT - 1) {
                out[(size_t)NB * LT * FH + (size_t)m * FH + feat]           = hv;
                out[(size_t)NB * LT * FH + NB * FH + (size_t)m * FH + feat] = c;
            }
        }

        // ---- grid barrier (all h writes visible before next step) ----
        __syncthreads();
        if (tid == 0) {
            __threadfence();
            atomicAdd(ctr, 1u);
            unsigned target = (unsigned)NRB * (unsigned)(t + 1);
            while (*(volatile unsigned*)ctr < target) { __nanosleep(64); }
            __threadfence();
        }
        __syncthreads();
    }
}

// ---------------- launch ----------------
extern "C" void kernel_launch(void* const* d_in, const int* in_sizes, int n_in,
                              void* d_out, int out_size)
{
    const float* src     = (const float*)d_in[0];
    const float* W_pre   = (const float*)d_in[1];
    const float* b_pre   = (const float*)d_in[2];
    const float* W_gat   = (const float*)d_in[3];
    const float* att_src = (const float*)d_in[4];
    const float* att_dst = (const float*)d_in[5];
    const float* b_gat   = (const float*)d_in[6];
    const float* W_ih    = (const float*)d_in[7];
    const float* W_hh    = (const float*)d_in[8];
    const float* b_ih    = (const float*)d_in[9];
    const float* b_hh    = (const float*)d_in[10];
    float* out = (float*)d_out;

    __half *Xp, *Wp;
    float *XWp, *Cp;
    cudaGetSymbolAddress((void**)&Xp,  g_Xp);
    cudaGetSymbolAddress((void**)&Wp,  g_Wp);
    cudaGetSymbolAddress((void**)&XWp, g_XW);
    cudaGetSymbolAddress((void**)&Cp,  g_c);

    cudaFuncSetAttribute(gemm_mma, cudaFuncAttributeMaxDynamicSharedMemorySize,
                         GEMM_SMEM);
    cudaFuncSetAttribute(lstm_persist, cudaFuncAttributeMaxDynamicSharedMemorySize,
                         PSMEM);

    // 0) prep: barrier counter, packed weights
    reset_ctr<<<1, 1>>>();
    pack_w<<<(GG * FH + 255) / 256, 256>>>(W_ih, Wp);
    pack_whh<<<(unsigned)(((size_t)GG * KR + 255) / 256), 256>>>(W_hh);

    // 1) GAT -> packed fp16 X
    gat_kernel<<<BG / 8, 256>>>(src, W_pre, b_pre, W_gat, att_src, att_dst, b_gat, Xp);

    // 2) big GEMM on tensor cores
    gemm_mma<<<dim3(GG / 128, BG / 128), 256, GEMM_SMEM>>>(Xp, Wp, XWp);

    // 3) whole recurrence: one persistent kernel
    lstm_persist<<<NRB, 256, PSMEM>>>(XWp, b_ih, b_hh, out, Cp);
}

// round 8
// speedup vs baseline: 3.9385x; 1.5828x over previous
#include <cuda_runtime.h>
#include <cuda_fp16.h>
#include <math.h>
#include <stdint.h>

// ---------------- problem constants ----------------
#define NB   128
#define LT   256
#define FH   768
#define GG   3072
#define BG   (NB*LT)

// ---- big hoisted GEMM (fp16 2-term) ----
#define K2   (2*FH)          // 1536
#define BK   32
#define NK2  (K2/BK)         // 48
#define ROWB 80
#define ATILE (128*ROWB)
#define STAGEB (2*ATILE)
#define NSTAGE 4
#define GEMM_SMEM (NSTAGE*STAGEB)   // 81920

// ---- persistent recurrent kernel (fp16 3-term, reuse-A) ----
#define KR2   1536           // h packed [hh|hl]
#define RBK   64             // k per chunk
#define RNCH  24             // A chunks (12 hh + 12 hl)
#define RROW  144            // smem row stride bytes
#define RA_BY (128*RROW)     // 18432 per A stage
#define RNST  4
#define WCHB  (32*RROW)      // 4608 per W chunk
#define WBASE (RNST*RA_BY)   // 73728
#define PSMEM (WBASE + RNCH*WCHB)   // 73728+110592 = 184320
#define NRB   96             // blocks = 3072/32

// ---------------- scratch (device globals) ----------------
__device__ __half g_Xp [(size_t)BG * K2];     // packed GAT out [ah | al]
__device__ __half g_Wp [(size_t)GG * K2];     // packed W_ih    [bh | bh]
__device__ __half g_Whp[(size_t)GG * KR2];    // permuted W_hh  [wh | wl]
__device__ __half g_hp [2][(size_t)NB * KR2]; // ping-pong packed h [hh|hl]
__device__ float  g_XW [(size_t)BG * GG];
__device__ unsigned g_ctr;                    // grid barrier counter

__constant__ int c_par[24] = {-1,0,0,0,1,2,3,4,5,6,7,8,9,9,9,12,13,14,16,17,18,19,20,21};

__device__ __forceinline__ float sigm(float x) { return 1.f / (1.f + expf(-x)); }

__device__ __forceinline__ uint32_t smem_u32(const void* p) {
    uint32_t a;
    asm("{ .reg .u64 t; cvta.to.shared.u64 t, %1; cvt.u32.u64 %0, t; }" : "=r"(a) : "l"(p));
    return a;
}

__device__ __forceinline__ void cp16(uint32_t s, const void* g) {
    asm volatile("cp.async.cg.shared.global [%0], [%1], 16;" :: "r"(s), "l"(g));
}

__device__ __forceinline__ void ldm_x4(uint32_t &r0, uint32_t &r1, uint32_t &r2,
                                       uint32_t &r3, uint32_t addr) {
    asm volatile("ldmatrix.sync.aligned.m8n8.x4.shared.b16 {%0,%1,%2,%3}, [%4];"
                 : "=r"(r0), "=r"(r1), "=r"(r2), "=r"(r3) : "r"(addr));
}

__device__ __forceinline__ void mma_f16(float* d, const uint32_t* a,
                                        const uint32_t* b) {
    asm volatile(
        "mma.sync.aligned.m16n8k16.row.col.f32.f16.f16.f32 "
        "{%0,%1,%2,%3}, {%4,%5,%6,%7}, {%8,%9}, {%0,%1,%2,%3};"
        : "+f"(d[0]), "+f"(d[1]), "+f"(d[2]), "+f"(d[3])
        : "r"(a[0]), "r"(a[1]), "r"(a[2]), "r"(a[3]), "r"(b[0]), "r"(b[1]));
}

// ---------------- small prep kernels ----------------
__global__ void reset_ctr() { g_ctr = 0u; }

__global__ void pack_w(const float* __restrict__ W, __half* __restrict__ Wp) {
    int i = blockIdx.x * 256 + threadIdx.x;
    if (i >= GG * FH) return;
    int n = i / FH, k = i % FH;
    __half wh = __float2half(W[i]);
    size_t o = (size_t)n * K2 + k;
    Wp[o] = wh; Wp[o + FH] = wh;
}

// Block b owns local rows r = g*8 + fi <-> W_hh row (g*768 + b*8 + fi).
// Layout: g_Whp[(b*32 + r)*KR2 + k], k<768: wh, k>=768: wl.
__global__ void pack_whh(const float* __restrict__ W) {
    size_t idx = (size_t)blockIdx.x * 256 + threadIdx.x;
    if (idx >= (size_t)GG * KR2) return;
    int k   = (int)(idx % KR2);
    int row = (int)(idx / KR2);
    int b = row >> 5, r = row & 31;
    int g = r >> 3, fi = r & 7;
    int seg = k / FH, kk = k % FH;
    float w = W[(size_t)(g * FH + b * 8 + fi) * FH + kk];
    __half wh = __float2half(w);
    g_Whp[idx] = (seg == 0) ? wh : __float2half(w - __half2float(wh));
}

// ---------------- GAT: one warp per graph, packs [ah | al] ----------------
__global__ __launch_bounds__(256) void gat_kernel(
    const float* __restrict__ src,
    const float* __restrict__ W_pre, const float* __restrict__ b_pre,
    const float* __restrict__ W_gat,
    const float* __restrict__ att_src, const float* __restrict__ att_dst,
    const float* __restrict__ b_gat,
    __half* __restrict__ Xp)
{
    __shared__ float Wg[32 * 32];
    __shared__ float xbuf[8][24][32];
    __shared__ float asd[8][24][2];

    int tid = threadIdx.x;
    for (int i = tid; i < 1024; i += 256) Wg[i] = W_gat[i];
    __syncthreads();

    int w = tid >> 5, h = tid & 31;
    int b = blockIdx.x * 8 + w;
    int n = b >> 8, l = b & 255;

    const float* s = src + (size_t)b * 72;
    float w0 = W_pre[h], w1 = W_pre[32 + h], w2 = W_pre[64 + h], bp = b_pre[h];

    #pragma unroll
    for (int j = 0; j < 24; j++) {
        float v = fmaf(s[j*3+2], w2, fmaf(s[j*3+1], w1, fmaf(s[j*3+0], w0, bp)));
        xbuf[w][j][h] = tanhf(v);
    }
    __syncwarp();

    float asrc = att_src[h], adst = att_dst[h];
    #pragma unroll
    for (int j = 0; j < 24; j++) {
        float acc = 0.f;
        #pragma unroll
        for (int k = 0; k < 32; k++) acc = fmaf(xbuf[w][j][k], Wg[k*32 + h], acc);
        float ps = acc * asrc, pd = acc * adst;
        #pragma unroll
        for (int o = 16; o > 0; o >>= 1) {
            ps += __shfl_xor_sync(0xffffffffu, ps, o);
            pd += __shfl_xor_sync(0xffffffffu, pd, o);
        }
        __syncwarp();
        xbuf[w][j][h] = acc;
        if (h == 0) { asd[w][j][0] = ps; asd[w][j][1] = pd; }
    }
    __syncwarp();

    float bg = b_gat[h];
    size_t rbase = (size_t)(l * 128 + n) * K2;
    #pragma unroll
    for (int j = 0; j < 24; j++) {
        int p = c_par[j];
        float g;
        if (p < 0) {
            g = xbuf[w][j][h];
        } else {
            float ad = asd[w][j][1];
            float es = ad + asd[w][j][0];
            float ep = ad + asd[w][p][0];
            es = es > 0.f ? es : 0.2f * es;
            ep = ep > 0.f ? ep : 0.2f * ep;
            float m  = fmaxf(es, ep);
            float ws = expf(es - m), wp = expf(ep - m);
            float inv = 1.f / (ws + wp);
            g = (ws * xbuf[w][j][h] + wp * xbuf[w][p][h]) * inv;
        }
        float v = g + bg;
        __half vh = __float2half(v);
        size_t o = rbase + j * 32 + h;
        Xp[o]      = vh;
        Xp[o + FH] = __float2half(v - __half2float(vh));
    }
}

// ---------------- big fp16 mma GEMM (proven 0.89ms) ----------------
__global__ __launch_bounds__(256, 2) void gemm_mma(
    const __half* __restrict__ Ap,
    const __half* __restrict__ Bp,
    float* __restrict__ C)
{
    extern __shared__ __align__(16) char sm[];

    const int tid  = threadIdx.x;
    const int lane = tid & 31;
    const int warp = tid >> 5;
    const int wm   = warp >> 2;
    const int wn   = warp & 3;
    const int n0   = blockIdx.x * 128;
    const int m0   = blockIdx.y * 128;

    const uint32_t smb = smem_u32(sm);

    const int ldRow = tid >> 2;
    const int ldSeg = tid & 3;
    const __half* gA = Ap + (size_t)(m0 + ldRow) * K2 + ldSeg * 8;
    const __half* gB = Bp + (size_t)(n0 + ldRow) * K2 + ldSeg * 8;
    const uint32_t stRow = ldRow * ROWB + ldSeg * 16;

    const uint32_t aOff = (uint32_t)((wm * 64 + (lane & 7) + ((lane >> 3) & 1) * 8) * ROWB
                                     + ((lane >> 4) & 1) * 16);
    const uint32_t bOff = (uint32_t)(ATILE + (wn * 32 + (lane & 7) + ((lane >> 4) & 1) * 8) * ROWB
                                     + ((lane >> 3) & 1) * 16);

    float acc[4][4][4];
    #pragma unroll
    for (int i = 0; i < 4; i++)
        #pragma unroll
        for (int j = 0; j < 4; j++)
            #pragma unroll
            for (int q = 0; q < 4; q++) acc[i][j][q] = 0.f;

    #pragma unroll
    for (int pc = 0; pc < NSTAGE - 1; pc++) {
        uint32_t sb = smb + pc * STAGEB;
        int ko = pc * BK;
        #pragma unroll
        for (int i = 0; i < 2; i++) {
            cp16(sb + stRow + i * 64 * ROWB,         gA + (size_t)i * 64 * K2 + ko);
            cp16(sb + ATILE + stRow + i * 64 * ROWB, gB + (size_t)i * 64 * K2 + ko);
        }
        asm volatile("cp.async.commit_group;");
    }

    for (int kc = 0; kc < NK2; kc++) {
        asm volatile("cp.async.wait_group %0;" :: "n"(NSTAGE - 2));
        __syncthreads();

        if (kc + NSTAGE - 1 < NK2) {
            uint32_t sb = smb + ((kc + NSTAGE - 1) & (NSTAGE - 1)) * STAGEB;
            int ko = (kc + NSTAGE - 1) * BK;
            #pragma unroll
            for (int i = 0; i < 2; i++) {
                cp16(sb + stRow + i * 64 * ROWB,         gA + (size_t)i * 64 * K2 + ko);
                cp16(sb + ATILE + stRow + i * 64 * ROWB, gB + (size_t)i * 64 * K2 + ko);
            }
        }
        asm volatile("cp.async.commit_group;");

        const uint32_t soff = smb + (kc & (NSTAGE - 1)) * STAGEB;
        #pragma unroll
        for (int ks = 0; ks < 2; ks++) {
            uint32_t a[4][4], bq[4][2];
            #pragma unroll
            for (int tm = 0; tm < 4; tm++)
                ldm_x4(a[tm][0], a[tm][1], a[tm][2], a[tm][3],
                       soff + aOff + tm * (16 * ROWB) + ks * 32);
            #pragma unroll
            for (int tb = 0; tb < 2; tb++) {
                uint32_t r0, r1, r2, r3;
                ldm_x4(r0, r1, r2, r3, soff + bOff + tb * (16 * ROWB) + ks * 32);
                bq[2*tb][0] = r0; bq[2*tb][1] = r1;
                bq[2*tb+1][0] = r2; bq[2*tb+1][1] = r3;
            }
            #pragma unroll
            for (int tm = 0; tm < 4; tm++)
                #pragma unroll
                for (int tn = 0; tn < 4; tn++)
                    mma_f16(acc[tm][tn], a[tm], bq[tn]);
        }
    }

    #pragma unroll
    for (int tm = 0; tm < 4; tm++) {
        int row = m0 + wm * 64 + tm * 16 + (lane >> 2);
        #pragma unroll
        for (int tn = 0; tn < 4; tn++) {
            int col = n0 + wn * 32 + tn * 8 + (lane & 3) * 2;
            float* p = C + (size_t)row * GG + col;
            *(float2*)p                    = make_float2(acc[tm][tn][0], acc[tm][tn][1]);
            *(float2*)(p + (size_t)8 * GG) = make_float2(acc[tm][tn][2], acc[tm][tn][3]);
        }
    }
}

// ---------------- persistent LSTM (reuse-A 3-term, register c) ----------------
__global__ __launch_bounds__(256) void lstm_persist(
    const float* __restrict__ xwbase,
    const float* __restrict__ bih, const float* __restrict__ bhh,
    float* __restrict__ out)
{
    extern __shared__ __align__(16) char sm[];
    const uint32_t smb = smem_u32(sm);

    const int tid  = threadIdx.x;
    const int lane = tid & 31;
    const int warp = tid >> 5;
    const int wm   = warp >> 1;          // 0..3: 32-row m strip
    const int wn   = warp & 1;           // 0..1: 16-row n strip
    const int b    = blockIdx.x;

    // epilogue cell mapping: feat-fast for coalescing
    const int efi = tid & 7;             // feature within block slice
    const int em0 = tid >> 3;            // base m (stride 32 over i)
    const int feat = b * 8 + efi;

    // ---- one-time: resident W slice (24 chunks: 12 wh + 12 wl) ----
    {
        const __half* Wb = g_Whp + (size_t)b * 32 * KR2;
        for (int i = tid; i < RNCH * 256; i += 256) {
            int chunk = i >> 8;
            int rem   = i & 255;
            int row   = rem >> 3, seg = rem & 7;
            cp16(smb + WBASE + chunk * WCHB + row * RROW + seg * 16,
                 Wb + (size_t)row * KR2 + chunk * RBK + seg * 8);
        }
        asm volatile("cp.async.commit_group;");
        asm volatile("cp.async.wait_group 0;");
    }

    // per-thread bias (4 gates of this thread's feature)
    float bias_r[4];
    #pragma unroll
    for (int g = 0; g < 4; g++) bias_r[g] = bih[g * FH + feat] + bhh[g * FH + feat];

    // register-resident cell state (4 cells: m = em0 + i*32)
    float creg[4] = {0.f, 0.f, 0.f, 0.f};

    __syncthreads();

    const uint32_t aOff = (uint32_t)((wm * 32 + (lane & 15)) * RROW
                                     + ((lane >> 4) & 1) * 16);
    const uint32_t bOffW = (uint32_t)((wn * 16 + (lane & 7) + ((lane >> 4) & 1) * 8) * RROW
                                      + ((lane >> 3) & 1) * 16);

    unsigned* ctr = &g_ctr;

    for (int t = 0; t < LT; t++) {
        const __half* hin   = g_hp[(t + 1) & 1];
        __half*       houtp = g_hp[t & 1];
        const float*  xw    = xwbase + (size_t)t * NB * GG;

        // ---- prefetch xw for this step's cells (hides under GEMM) ----
        float xwv[4][4];
        #pragma unroll
        for (int i = 0; i < 4; i++) {
            const float* xwr = xw + (size_t)(em0 + i * 32) * GG + feat;
            xwv[i][0] = xwr[0];
            xwv[i][1] = xwr[FH];
            xwv[i][2] = xwr[2 * FH];
            xwv[i][3] = xwr[3 * FH];
        }

        float acc[2][2][4];
        #pragma unroll
        for (int i = 0; i < 2; i++)
            #pragma unroll
            for (int j = 0; j < 2; j++)
                #pragma unroll
                for (int q = 0; q < 4; q++) acc[i][j][q] = 0.f;

        if (t > 0) {
            // prologue: A chunks 0..RNST-2
            #pragma unroll
            for (int pc = 0; pc < RNST - 1; pc++) {
                uint32_t sb = smb + pc * RA_BY;
                int ko = pc * RBK;
                #pragma unroll
                for (int i = 0; i < 4; i++) {
                    int slot = tid + i * 256;
                    int row = slot >> 3, seg = slot & 7;
                    cp16(sb + row * RROW + seg * 16,
                         hin + (size_t)row * KR2 + ko + seg * 8);
                }
                asm volatile("cp.async.commit_group;");
            }

            for (int kc = 0; kc < RNCH; kc++) {
                asm volatile("cp.async.wait_group %0;" :: "n"(RNST - 2));
                __syncthreads();

                if (kc + RNST - 1 < RNCH) {
                    uint32_t sb = smb + ((kc + RNST - 1) & (RNST - 1)) * RA_BY;
                    int ko = (kc + RNST - 1) * RBK;
                    #pragma unroll
                    for (int i = 0; i < 4; i++) {
                        int slot = tid + i * 256;
                        int row = slot >> 3, seg = slot & 7;
                        cp16(sb + row * RROW + seg * 16,
                             hin + (size_t)row * KR2 + ko + seg * 8);
                    }
                }
                asm volatile("cp.async.commit_group;");

                const uint32_t soff = smb + (kc & (RNST - 1)) * RA_BY;
                const bool two = (kc < 12);
                const uint32_t woffH = smb + WBASE + (two ? kc : kc - 12) * WCHB;
                const uint32_t woffL = smb + WBASE + (kc + 12) * WCHB; // valid iff two

                #pragma unroll
                for (int ks = 0; ks < RBK / 16; ks++) {
                    uint32_t a[2][4], bq[2][2];
                    #pragma unroll
                    for (int tm = 0; tm < 2; tm++)
                        ldm_x4(a[tm][0], a[tm][1], a[tm][2], a[tm][3],
                               soff + aOff + tm * (16 * RROW) + ks * 32);
                    {
                        uint32_t r0, r1, r2, r3;
                        ldm_x4(r0, r1, r2, r3, woffH + bOffW + ks * 32);
                        bq[0][0] = r0; bq[0][1] = r1;
                        bq[1][0] = r2; bq[1][1] = r3;
                    }
                    #pragma unroll
                    for (int tm = 0; tm < 2; tm++)
                        #pragma unroll
                        for (int tn = 0; tn < 2; tn++)
                            mma_f16(acc[tm][tn], a[tm], bq[tn]);

                    if (two) {
                        uint32_t r0, r1, r2, r3;
                        ldm_x4(r0, r1, r2, r3, woffL + bOffW + ks * 32);
                        bq[0][0] = r0; bq[0][1] = r1;
                        bq[1][0] = r2; bq[1][1] = r3;
                        #pragma unroll
                        for (int tm = 0; tm < 2; tm++)
                            #pragma unroll
                            for (int tn = 0; tn < 2; tn++)
                                mma_f16(acc[tm][tn], a[tm], bq[tn]);
                    }
                }
            }
            asm volatile("cp.async.wait_group 0;");
        }
        __syncthreads();

        // gate tile overlay in A-stage region: Gt[32 n][132 m] fp32
        float* Gt = (float*)sm;
        #pragma unroll
        for (int tm = 0; tm < 2; tm++) {
            int m = wm * 32 + tm * 16 + (lane >> 2);
            #pragma unroll
            for (int tn = 0; tn < 2; tn++) {
                int n = wn * 16 + tn * 8 + (lane & 3) * 2;
                Gt[n * 132 + m]           = acc[tm][tn][0];
                Gt[(n + 1) * 132 + m]     = acc[tm][tn][1];
                Gt[n * 132 + m + 8]       = acc[tm][tn][2];
                Gt[(n + 1) * 132 + m + 8] = acc[tm][tn][3];
            }
        }
        __syncthreads();

        // fused pointwise: feat-fast mapping, coalesced I/O, register c
        #pragma unroll
        for (int i = 0; i < 4; i++) {
            int m = em0 + i * 32;

            float gi = Gt[(0*8 + efi) * 132 + m] + xwv[i][0] + bias_r[0];
            float gf = Gt[(1*8 + efi) * 132 + m] + xwv[i][1] + bias_r[1];
            float gg = Gt[(2*8 + efi) * 132 + m] + xwv[i][2] + bias_r[2];
            float go = Gt[(3*8 + efi) * 132 + m] + xwv[i][3] + bias_r[3];

            float c  = sigm(gf) * creg[i] + sigm(gi) * tanhf(gg);
            float hv = sigm(go) * tanhf(c);
            creg[i] = c;

            out[((size_t)m * LT + t) * FH + feat] = hv;

            __half hh = __float2half(hv);
            size_t hb = (size_t)m * KR2 + feat;
            houtp[hb]      = hh;
            houtp[hb + FH] = __float2half(hv - __half2float(hh));

            if (t == LT - 1) {
                out[(size_t)NB * LT * FH + (size_t)m * FH + feat]           = hv;
                out[(size_t)NB * LT * FH + NB * FH + (size_t)m * FH + feat] = c;
            }
        }

        // ---- grid barrier ----
        __syncthreads();
        if (tid == 0) {
            __threadfence();
            atomicAdd(ctr, 1u);
            unsigned target = (unsigned)NRB * (unsigned)(t + 1);
            while (*(volatile unsigned*)ctr < target) { __nanosleep(64); }
            __threadfence();
        }
        __syncthreads();
    }
}

// ---------------- launch ----------------
extern "C" void kernel_launch(void* const* d_in, const int* in_sizes, int n_in,
                              void* d_out, int out_size)
{
    const float* src     = (const float*)d_in[0];
    const float* W_pre   = (const float*)d_in[1];
    const float* b_pre   = (const float*)d_in[2];
    const float* W_gat   = (const float*)d_in[3];
    const float* att_src = (const float*)d_in[4];
    const float* att_dst = (const float*)d_in[5];
    const float* b_gat   = (const float*)d_in[6];
    const float* W_ih    = (const float*)d_in[7];
    const float* W_hh    = (const float*)d_in[8];
    const float* b_ih    = (const float*)d_in[9];
    const float* b_hh    = (const float*)d_in[10];
    float* out = (float*)d_out;

    __half *Xp, *Wp;
    float *XWp;
    cudaGetSymbolAddress((void**)&Xp,  g_Xp);
    cudaGetSymbolAddress((void**)&Wp,  g_Wp);
    cudaGetSymbolAddress((void**)&XWp, g_XW);

    cudaFuncSetAttribute(gemm_mma, cudaFuncAttributeMaxDynamicSharedMemorySize,
                         GEMM_SMEM);
    cudaFuncSetAttribute(lstm_persist, cudaFuncAttributeMaxDynamicSharedMemorySize,
                         PSMEM);

    // 0) prep
    reset_ctr<<<1, 1>>>();
    pack_w<<<(GG * FH + 255) / 256, 256>>>(W_ih, Wp);
    pack_whh<<<(unsigned)(((size_t)GG * KR2 + 255) / 256), 256>>>(W_hh);

    // 1) GAT -> packed fp16 X
    gat_kernel<<<BG / 8, 256>>>(src, W_pre, b_pre, W_gat, att_src, att_dst, b_gat, Xp);

    // 2) big GEMM on tensor cores
    gemm_mma<<<dim3(GG / 128, BG / 128), 256, GEMM_SMEM>>>(Xp, Wp, XWp);

    // 3) whole recurrence: one persistent kernel
    lstm_persist<<<NRB, 256, PSMEM>>>(XWp, b_ih, b_hh, out);
}

// round 9
// speedup vs baseline: 4.7358x; 1.2024x over previous
#include <cuda_runtime.h>
#include <cuda_fp16.h>
#include <math.h>
#include <stdint.h>

// ---------------- problem constants ----------------
#define NB   128
#define LT   256
#define FH   768
#define GG   3072
#define BG   (NB*LT)

// ---- big hoisted GEMM (fp16 2-term) ----
#define K2   (2*FH)          // 1536
#define BK   32
#define NK2  (K2/BK)         // 48
#define ROWB 80
#define ATILE (128*ROWB)
#define STAGEB (2*ATILE)     // 20480
#define GNST 8               // producer-role stages (1 CTA/SM -> deep pipeline)

// ---- persistent recurrent role (fp16 3-term, reuse-A) ----
#define KR2   1536           // h packed [hh|hl]
#define RBK   64
#define RNCH  24             // 12 hh + 12 hl chunks
#define RROW  144
#define RA_BY (128*RROW)     // 18432 per A stage
#define RNST  4
#define WCHB  (32*RROW)      // 4608 per W chunk
#define WBASE (RNST*RA_BY)   // 73728
#define PSMEM (WBASE + RNCH*WCHB)   // 184320
#define NRB   96             // lstm-role blocks
#define NGB   52             // gemm-role blocks
#define NTILE (24*LT)        // 6144 gemm tiles
#define MEGA_SMEM PSMEM      // >= GNST*STAGEB (163840)

// ---------------- scratch (device globals) ----------------
__device__ __half g_Xp [(size_t)BG * K2];
__device__ __half g_Wp [(size_t)GG * K2];
__device__ __half g_Whp[(size_t)GG * KR2];
__device__ __half g_hp [2][(size_t)NB * KR2];
__device__ float  g_XW [(size_t)BG * GG];
__device__ unsigned g_ctr;
__device__ int      g_flag[LT];

__constant__ int c_par[24] = {-1,0,0,0,1,2,3,4,5,6,7,8,9,9,9,12,13,14,16,17,18,19,20,21};

__device__ __forceinline__ float sigm(float x) { return 1.f / (1.f + expf(-x)); }

__device__ __forceinline__ uint32_t smem_u32(const void* p) {
    uint32_t a;
    asm("{ .reg .u64 t; cvta.to.shared.u64 t, %1; cvt.u32.u64 %0, t; }" : "=r"(a) : "l"(p));
    return a;
}

__device__ __forceinline__ void cp16(uint32_t s, const void* g) {
    asm volatile("cp.async.cg.shared.global [%0], [%1], 16;" :: "r"(s), "l"(g));
}

__device__ __forceinline__ void ldm_x4(uint32_t &r0, uint32_t &r1, uint32_t &r2,
                                       uint32_t &r3, uint32_t addr) {
    asm volatile("ldmatrix.sync.aligned.m8n8.x4.shared.b16 {%0,%1,%2,%3}, [%4];"
                 : "=r"(r0), "=r"(r1), "=r"(r2), "=r"(r3) : "r"(addr));
}

__device__ __forceinline__ void mma_f16(float* d, const uint32_t* a,
                                        const uint32_t* b) {
    asm volatile(
        "mma.sync.aligned.m16n8k16.row.col.f32.f16.f16.f32 "
        "{%0,%1,%2,%3}, {%4,%5,%6,%7}, {%8,%9}, {%0,%1,%2,%3};"
        : "+f"(d[0]), "+f"(d[1]), "+f"(d[2]), "+f"(d[3])
        : "r"(a[0]), "r"(a[1]), "r"(a[2]), "r"(a[3]), "r"(b[0]), "r"(b[1]));
}

// ---------------- small prep kernels ----------------
__global__ void reset_ctr() {
    if (threadIdx.x == 0) g_ctr = 0u;
    if (threadIdx.x < LT) g_flag[threadIdx.x] = 0;
}

__global__ void pack_w(const float* __restrict__ W, __half* __restrict__ Wp) {
    int i = blockIdx.x * 256 + threadIdx.x;
    if (i >= GG * FH) return;
    int n = i / FH, k = i % FH;
    __half wh = __float2half(W[i]);
    size_t o = (size_t)n * K2 + k;
    Wp[o] = wh; Wp[o + FH] = wh;
}

__global__ void pack_whh(const float* __restrict__ W) {
    size_t idx = (size_t)blockIdx.x * 256 + threadIdx.x;
    if (idx >= (size_t)GG * KR2) return;
    int k   = (int)(idx % KR2);
    int row = (int)(idx / KR2);
    int b = row >> 5, r = row & 31;
    int g = r >> 3, fi = r & 7;
    int seg = k / FH, kk = k % FH;
    float w = W[(size_t)(g * FH + b * 8 + fi) * FH + kk];
    __half wh = __float2half(w);
    g_Whp[idx] = (seg == 0) ? wh : __float2half(w - __half2float(wh));
}

// ---------------- GAT: one warp per graph, packs [ah | al] ----------------
__global__ __launch_bounds__(256) void gat_kernel(
    const float* __restrict__ src,
    const float* __restrict__ W_pre, const float* __restrict__ b_pre,
    const float* __restrict__ W_gat,
    const float* __restrict__ att_src, const float* __restrict__ att_dst,
    const float* __restrict__ b_gat,
    __half* __restrict__ Xp)
{
    __shared__ float Wg[32 * 32];
    __shared__ float xbuf[8][24][32];
    __shared__ float asd[8][24][2];

    int tid = threadIdx.x;
    for (int i = tid; i < 1024; i += 256) Wg[i] = W_gat[i];
    __syncthreads();

    int w = tid >> 5, h = tid & 31;
    int b = blockIdx.x * 8 + w;
    int n = b >> 8, l = b & 255;

    const float* s = src + (size_t)b * 72;
    float w0 = W_pre[h], w1 = W_pre[32 + h], w2 = W_pre[64 + h], bp = b_pre[h];

    #pragma unroll
    for (int j = 0; j < 24; j++) {
        float v = fmaf(s[j*3+2], w2, fmaf(s[j*3+1], w1, fmaf(s[j*3+0], w0, bp)));
        xbuf[w][j][h] = tanhf(v);
    }
    __syncwarp();

    float asrc = att_src[h], adst = att_dst[h];
    #pragma unroll
    for (int j = 0; j < 24; j++) {
        float acc = 0.f;
        #pragma unroll
        for (int k = 0; k < 32; k++) acc = fmaf(xbuf[w][j][k], Wg[k*32 + h], acc);
        float ps = acc * asrc, pd = acc * adst;
        #pragma unroll
        for (int o = 16; o > 0; o >>= 1) {
            ps += __shfl_xor_sync(0xffffffffu, ps, o);
            pd += __shfl_xor_sync(0xffffffffu, pd, o);
        }
        __syncwarp();
        xbuf[w][j][h] = acc;
        if (h == 0) { asd[w][j][0] = ps; asd[w][j][1] = pd; }
    }
    __syncwarp();

    float bg = b_gat[h];
    size_t rbase = (size_t)(l * 128 + n) * K2;
    #pragma unroll
    for (int j = 0; j < 24; j++) {
        int p = c_par[j];
        float g;
        if (p < 0) {
            g = xbuf[w][j][h];
        } else {
            float ad = asd[w][j][1];
            float es = ad + asd[w][j][0];
            float ep = ad + asd[w][p][0];
            es = es > 0.f ? es : 0.2f * es;
            ep = ep > 0.f ? ep : 0.2f * ep;
            float m  = fmaxf(es, ep);
            float ws = expf(es - m), wp = expf(ep - m);
            float inv = 1.f / (ws + wp);
            g = (ws * xbuf[w][j][h] + wp * xbuf[w][p][h]) * inv;
        }
        float v = g + bg;
        __half vh = __float2half(v);
        size_t o = rbase + j * 32 + h;
        Xp[o]      = vh;
        Xp[o + FH] = __float2half(v - __half2float(vh));
    }
}

// ---------------- mega kernel: producer gemm (52 blocks) + lstm (96 blocks) ----
__global__ __launch_bounds__(256, 1) void mega(
    const float* __restrict__ bih, const float* __restrict__ bhh,
    float* __restrict__ out)
{
    extern __shared__ __align__(16) char sm[];
    const uint32_t smb = smem_u32(sm);

    const int tid  = threadIdx.x;
    const int lane = tid & 31;
    const int warp = tid >> 5;

    if (blockIdx.x >= NRB) {
        // ================= producer role: big GEMM tiles, y-major =================
        const int gb = blockIdx.x - NRB;
        const __half* Ap = g_Xp;
        const __half* Bp = g_Wp;
        float* C = g_XW;

        const int wm = warp >> 2;
        const int wn = warp & 3;
        const int ldRow = tid >> 2;
        const int ldSeg = tid & 3;
        const uint32_t stRow = ldRow * ROWB + ldSeg * 16;
        const uint32_t aOff = (uint32_t)((wm * 64 + (lane & 7) + ((lane >> 3) & 1) * 8) * ROWB
                                         + ((lane >> 4) & 1) * 16);
        const uint32_t bOff = (uint32_t)(ATILE + (wn * 32 + (lane & 7) + ((lane >> 4) & 1) * 8) * ROWB
                                         + ((lane >> 3) & 1) * 16);

        for (int tile = gb; tile < NTILE; tile += NGB) {
            const int y = tile / 24;           // == timestep t
            const int x = tile % 24;
            const int m0 = y * 128;
            const int n0 = x * 128;

            const __half* gA = Ap + (size_t)(m0 + ldRow) * K2 + ldSeg * 8;
            const __half* gB = Bp + (size_t)(n0 + ldRow) * K2 + ldSeg * 8;

            float acc[4][4][4];
            #pragma unroll
            for (int i = 0; i < 4; i++)
                #pragma unroll
                for (int j = 0; j < 4; j++)
                    #pragma unroll
                    for (int q = 0; q < 4; q++) acc[i][j][q] = 0.f;

            #pragma unroll
            for (int pc = 0; pc < GNST - 1; pc++) {
                uint32_t sb = smb + pc * STAGEB;
                int ko = pc * BK;
                #pragma unroll
                for (int i = 0; i < 2; i++) {
                    cp16(sb + stRow + i * 64 * ROWB,         gA + (size_t)i * 64 * K2 + ko);
                    cp16(sb + ATILE + stRow + i * 64 * ROWB, gB + (size_t)i * 64 * K2 + ko);
                }
                asm volatile("cp.async.commit_group;");
            }

            for (int kc = 0; kc < NK2; kc++) {
                asm volatile("cp.async.wait_group %0;" :: "n"(GNST - 2));
                __syncthreads();

                if (kc + GNST - 1 < NK2) {
                    uint32_t sb = smb + ((kc + GNST - 1) & (GNST - 1)) * STAGEB;
                    int ko = (kc + GNST - 1) * BK;
                    #pragma unroll
                    for (int i = 0; i < 2; i++) {
                        cp16(sb + stRow + i * 64 * ROWB,         gA + (size_t)i * 64 * K2 + ko);
                        cp16(sb + ATILE + stRow + i * 64 * ROWB, gB + (size_t)i * 64 * K2 + ko);
                    }
                }
                asm volatile("cp.async.commit_group;");

                const uint32_t soff = smb + (kc & (GNST - 1)) * STAGEB;
                #pragma unroll
                for (int ks = 0; ks < 2; ks++) {
                    uint32_t a[4][4], bq[4][2];
                    #pragma unroll
                    for (int tm = 0; tm < 4; tm++)
                        ldm_x4(a[tm][0], a[tm][1], a[tm][2], a[tm][3],
                               soff + aOff + tm * (16 * ROWB) + ks * 32);
                    #pragma unroll
                    for (int tb = 0; tb < 2; tb++) {
                        uint32_t r0, r1, r2, r3;
                        ldm_x4(r0, r1, r2, r3, soff + bOff + tb * (16 * ROWB) + ks * 32);
                        bq[2*tb][0] = r0; bq[2*tb][1] = r1;
                        bq[2*tb+1][0] = r2; bq[2*tb+1][1] = r3;
                    }
                    #pragma unroll
                    for (int tm = 0; tm < 4; tm++)
                        #pragma unroll
                        for (int tn = 0; tn < 4; tn++)
                            mma_f16(acc[tm][tn], a[tm], bq[tn]);
                }
            }
            asm volatile("cp.async.wait_group 0;");

            #pragma unroll
            for (int tm = 0; tm < 4; tm++) {
                int row = m0 + wm * 64 + tm * 16 + (lane >> 2);
                #pragma unroll
                for (int tn = 0; tn < 4; tn++) {
                    int col = n0 + wn * 32 + tn * 8 + (lane & 3) * 2;
                    float* p = C + (size_t)row * GG + col;
                    *(float2*)p                    = make_float2(acc[tm][tn][0], acc[tm][tn][1]);
                    *(float2*)(p + (size_t)8 * GG) = make_float2(acc[tm][tn][2], acc[tm][tn][3]);
                }
            }

            __threadfence();          // all threads: release C stores
            __syncthreads();
            if (tid == 0) atomicAdd(&g_flag[y], 1);
            __syncthreads();
        }
        return;
    }

    // ================= consumer role: persistent LSTM =================
    const int wm = warp >> 1;            // 0..3: 32-row m strip
    const int wn = warp & 1;             // 0..1: 16-row n strip
    const int b  = blockIdx.x;

    const int efi = tid & 7;
    const int em0 = tid >> 3;
    const int feat = b * 8 + efi;

    // one-time resident W slice
    {
        const __half* Wb = g_Whp + (size_t)b * 32 * KR2;
        for (int i = tid; i < RNCH * 256; i += 256) {
            int chunk = i >> 8;
            int rem   = i & 255;
            int row   = rem >> 3, seg = rem & 7;
            cp16(smb + WBASE + chunk * WCHB + row * RROW + seg * 16,
                 Wb + (size_t)row * KR2 + chunk * RBK + seg * 8);
        }
        asm volatile("cp.async.commit_group;");
        asm volatile("cp.async.wait_group 0;");
    }

    float bias_r[4];
    #pragma unroll
    for (int g = 0; g < 4; g++) bias_r[g] = bih[g * FH + feat] + bhh[g * FH + feat];

    float creg[4] = {0.f, 0.f, 0.f, 0.f};

    __syncthreads();

    const uint32_t aOff = (uint32_t)((wm * 32 + (lane & 15)) * RROW
                                     + ((lane >> 4) & 1) * 16);
    const uint32_t bOffW = (uint32_t)((wn * 16 + (lane & 7) + ((lane >> 4) & 1) * 8) * RROW
                                      + ((lane >> 3) & 1) * 16);

    unsigned* ctr = &g_ctr;
    const float* xwbase = g_XW;

    for (int t = 0; t < LT; t++) {
        const __half* hin   = g_hp[(t + 1) & 1];
        __half*       houtp = g_hp[t & 1];
        const float*  xw    = xwbase + (size_t)t * NB * GG;

        // ---- wait for xw[t] tiles from producers ----
        if (tid == 0) {
            while (*(volatile int*)&g_flag[t] < 24) { __nanosleep(128); }
            __threadfence();
        }
        __syncthreads();

        // prefetch xw values for this step's cells
        float xwv[4][4];
        #pragma unroll
        for (int i = 0; i < 4; i++) {
            const float* xwr = xw + (size_t)(em0 + i * 32) * GG + feat;
            xwv[i][0] = xwr[0];
            xwv[i][1] = xwr[FH];
            xwv[i][2] = xwr[2 * FH];
            xwv[i][3] = xwr[3 * FH];
        }

        float acc[2][2][4];
        #pragma unroll
        for (int i = 0; i < 2; i++)
            #pragma unroll
            for (int j = 0; j < 2; j++)
                #pragma unroll
                for (int q = 0; q < 4; q++) acc[i][j][q] = 0.f;

        if (t > 0) {
            #pragma unroll
            for (int pc = 0; pc < RNST - 1; pc++) {
                uint32_t sb = smb + pc * RA_BY;
                int ko = pc * RBK;
                #pragma unroll
                for (int i = 0; i < 4; i++) {
                    int slot = tid + i * 256;
                    int row = slot >> 3, seg = slot & 7;
                    cp16(sb + row * RROW + seg * 16,
                         hin + (size_t)row * KR2 + ko + seg * 8);
                }
                asm volatile("cp.async.commit_group;");
            }

            for (int kc = 0; kc < RNCH; kc++) {
                asm volatile("cp.async.wait_group %0;" :: "n"(RNST - 2));
                __syncthreads();

                if (kc + RNST - 1 < RNCH) {
                    uint32_t sb = smb + ((kc + RNST - 1) & (RNST - 1)) * RA_BY;
                    int ko = (kc + RNST - 1) * RBK;
                    #pragma unroll
                    for (int i = 0; i < 4; i++) {
                        int slot = tid + i * 256;
                        int row = slot >> 3, seg = slot & 7;
                        cp16(sb + row * RROW + seg * 16,
                             hin + (size_t)row * KR2 + ko + seg * 8);
                    }
                }
                asm volatile("cp.async.commit_group;");

                const uint32_t soff = smb + (kc & (RNST - 1)) * RA_BY;
                const bool two = (kc < 12);
                const uint32_t woffH = smb + WBASE + (two ? kc : kc - 12) * WCHB;
                const uint32_t woffL = smb + WBASE + (kc + 12) * WCHB;

                #pragma unroll
                for (int ks = 0; ks < RBK / 16; ks++) {
                    uint32_t a[2][4], bq[2][2];
                    #pragma unroll
                    for (int tm = 0; tm < 2; tm++)
                        ldm_x4(a[tm][0], a[tm][1], a[tm][2], a[tm][3],
                               soff + aOff + tm * (16 * RROW) + ks * 32);
                    {
                        uint32_t r0, r1, r2, r3;
                        ldm_x4(r0, r1, r2, r3, woffH + bOffW + ks * 32);
                        bq[0][0] = r0; bq[0][1] = r1;
                        bq[1][0] = r2; bq[1][1] = r3;
                    }
                    #pragma unroll
                    for (int tm = 0; tm < 2; tm++)
                        #pragma unroll
                        for (int tn = 0; tn < 2; tn++)
                            mma_f16(acc[tm][tn], a[tm], bq[tn]);

                    if (two) {
                        uint32_t r0, r1, r2, r3;
                        ldm_x4(r0, r1, r2, r3, woffL + bOffW + ks * 32);
                        bq[0][0] = r0; bq[0][1] = r1;
                        bq[1][0] = r2; bq[1][1] = r3;
                        #pragma unroll
                        for (int tm = 0; tm < 2; tm++)
                            #pragma unroll
                            for (int tn = 0; tn < 2; tn++)
                                mma_f16(acc[tm][tn], a[tm], bq[tn]);
                    }
                }
            }
            asm volatile("cp.async.wait_group 0;");
        }
        __syncthreads();

        float* Gt = (float*)sm;
        #pragma unroll
        for (int tm = 0; tm < 2; tm++) {
            int m = wm * 32 + tm * 16 + (lane >> 2);
            #pragma unroll
            for (int tn = 0; tn < 2; tn++) {
                int n = wn * 16 + tn * 8 + (lane & 3) * 2;
                Gt[n * 132 + m]           = acc[tm][tn][0];
                Gt[(n + 1) * 132 + m]     = acc[tm][tn][1];
                Gt[n * 132 + m + 8]       = acc[tm][tn][2];
                Gt[(n + 1) * 132 + m + 8] = acc[tm][tn][3];
            }
        }
        __syncthreads();

        #pragma unroll
        for (int i = 0; i < 4; i++) {
            int m = em0 + i * 32;

            float gi = Gt[(0*8 + efi) * 132 + m] + xwv[i][0] + bias_r[0];
            float gf = Gt[(1*8 + efi) * 132 + m] + xwv[i][1] + bias_r[1];
            float gg = Gt[(2*8 + efi) * 132 + m] + xwv[i][2] + bias_r[2];
            float go = Gt[(3*8 + efi) * 132 + m] + xwv[i][3] + bias_r[3];

            float c  = sigm(gf) * creg[i] + sigm(gi) * tanhf(gg);
            float hv = sigm(go) * tanhf(c);
            creg[i] = c;

            out[((size_t)m * LT + t) * FH + feat] = hv;

            __half hh = __float2half(hv);
            size_t hb = (size_t)m * KR2 + feat;
            houtp[hb]      = hh;
            houtp[hb + FH] = __float2half(hv - __half2float(hh));

            if (t == LT - 1) {
                out[(size_t)NB * LT * FH + (size_t)m * FH + feat]           = hv;
                out[(size_t)NB * LT * FH + NB * FH + (size_t)m * FH + feat] = c;
            }
        }

        // ---- grid barrier over 96 lstm blocks ----
        __syncthreads();
        if (tid == 0) {
            __threadfence();
            atomicAdd(ctr, 1u);
            unsigned target = (unsigned)NRB * (unsigned)(t + 1);
            while (*(volatile unsigned*)ctr < target) { __nanosleep(64); }
            __threadfence();
        }
        __syncthreads();
    }
}

// ---------------- launch ----------------
extern "C" void kernel_launch(void* const* d_in, const int* in_sizes, int n_in,
                              void* d_out, int out_size)
{
    const float* src     = (const float*)d_in[0];
    const float* W_pre   = (const float*)d_in[1];
    const float* b_pre   = (const float*)d_in[2];
    const float* W_gat   = (const float*)d_in[3];
    const float* att_src = (const float*)d_in[4];
    const float* att_dst = (const float*)d_in[5];
    const float* b_gat   = (const float*)d_in[6];
    const float* W_ih    = (const float*)d_in[7];
    const float* W_hh    = (const float*)d_in[8];
    const float* b_ih    = (const float*)d_in[9];
    const float* b_hh    = (const float*)d_in[10];
    float* out = (float*)d_out;

    __half *Xp, *Wp;
    cudaGetSymbolAddress((void**)&Xp,  g_Xp);
    cudaGetSymbolAddress((void**)&Wp,  g_Wp);

    cudaFuncSetAttribute(mega, cudaFuncAttributeMaxDynamicSharedMemorySize,
                         MEGA_SMEM);

    // 0) prep
    reset_ctr<<<1, 256>>>();
    pack_w<<<(GG * FH + 255) / 256, 256>>>(W_ih, Wp);
    pack_whh<<<(unsigned)(((size_t)GG * KR2 + 255) / 256), 256>>>(W_hh);

    // 1) GAT -> packed fp16 X
    gat_kernel<<<BG / 8, 256>>>(src, W_pre, b_pre, W_gat, att_src, att_dst, b_gat, Xp);

    // 2) fused producer-GEMM + persistent-LSTM mega kernel
    mega<<<NRB + NGB, 256, MEGA_SMEM>>>(b_ih, b_hh, out);
}